// round 1
// baseline (speedup 1.0000x reference)
#include <cuda_runtime.h>
#include <cstdint>
#include <cstddef>

#define B_SZ 4
#define N_SZ 4096
#define C_SZ 128
#define KCH  3
#define KC   (KCH * C_SZ)                       // 384
#define NC   ((size_t)N_SZ * C_SZ)              // 524288
#define ZBATCH ((size_t)KCH * N_SZ * C_SZ)      // 1572864

static constexpr float LR = 2.0f / (2.0f + 1e-6f);

// Scratch (device globals: no runtime allocation allowed)
__device__ float g_Z[(size_t)B_SZ * KCH * N_SZ * C_SZ];  // [B][K][N][C]  (24 MB)
__device__ float g_coef[B_SZ * N_SZ];                    // lr*deg - 1
__device__ float g_Wt[KC * C_SZ];                        // W^T  [384][128]

// ---------------------------------------------------------------------------
// degree + coef:  deg[b][m] = sum_n adj[b][n][m];  coef = lr*deg - 1
// ---------------------------------------------------------------------------
__global__ void deg_kernel(const float* __restrict__ adj) {
    int b  = blockIdx.y;
    int m4 = blockIdx.x * blockDim.x + threadIdx.x;      // 0..1023
    const float* a = adj + (size_t)b * N_SZ * N_SZ + (size_t)m4 * 4;
    float4 s = make_float4(0.f, 0.f, 0.f, 0.f);
    #pragma unroll 4
    for (int n = 0; n < N_SZ; n++) {
        float4 v = *(const float4*)(a + (size_t)n * N_SZ);
        s.x += v.x; s.y += v.y; s.z += v.z; s.w += v.w;
    }
    float* c = g_coef + b * N_SZ + m4 * 4;
    c[0] = LR * s.x - 1.0f;
    c[1] = LR * s.y - 1.0f;
    c[2] = LR * s.z - 1.0f;
    c[3] = LR * s.w - 1.0f;
}

// ---------------------------------------------------------------------------
// copy x into Z slice 0 (the flattened-view layout needs it materialized)
// ---------------------------------------------------------------------------
__global__ void copyx_kernel(const float* __restrict__ x) {
    size_t i   = (size_t)blockIdx.x * blockDim.x + threadIdx.x;  // over float4s
    size_t b   = i / (NC / 4);
    size_t rem = i % (NC / 4);
    float4 v = ((const float4*)x)[i];
    ((float4*)g_Z)[b * (ZBATCH / 4) + rem] = v;
}

// ---------------------------------------------------------------------------
// transpose W [128][384] -> g_Wt [384][128]
// ---------------------------------------------------------------------------
__global__ void wt_kernel(const float* __restrict__ W) {
    int i = blockIdx.x * blockDim.x + threadIdx.x;  // 49152
    int o = i / KC, k = i % KC;
    g_Wt[k * C_SZ + o] = W[i];
}

// ---------------------------------------------------------------------------
// tf32 helpers
// ---------------------------------------------------------------------------
__device__ __forceinline__ float to_tf32(float x) {
    uint32_t u;
    asm("cvt.rna.tf32.f32 %0, %1;" : "=r"(u) : "f"(x));
    return __uint_as_float(u);
}

__device__ __forceinline__ void mma_tf32(float* d, const uint32_t* a, const uint32_t* b) {
    asm volatile(
        "mma.sync.aligned.m16n8k8.row.col.f32.tf32.tf32.f32 "
        "{%0,%1,%2,%3}, {%4,%5,%6,%7}, {%8,%9}, {%0,%1,%2,%3};\n"
        : "+f"(d[0]), "+f"(d[1]), "+f"(d[2]), "+f"(d[3])
        : "r"(a[0]), "r"(a[1]), "r"(a[2]), "r"(a[3]), "r"(b[0]), "r"(b[1]));
}

// ---------------------------------------------------------------------------
// Chebyshev step GEMM (tf32 tensor cores) + fused elementwise epilogue.
//   S[n][c] = sum_m adj[b][n][m] * z[b][m][c]
//   STEP 1: out = coef*z           - lr*S            -> g_Z slice 1   (z = x)
//   STEP 2: out = 2*coef*z - 2*lr*S - x              -> g_Z slice 2   (z = Z1)
// Block tile 128x128x32, 8 warps, warp tile 64x32, mma m16n8k8.
// ---------------------------------------------------------------------------
template <int STEP>
__global__ void __launch_bounds__(256, 2)
cheb_mma_kernel(const float* __restrict__ adj, const float* __restrict__ x) {
    constexpr float alpha = (STEP == 1) ? 1.0f : 2.0f;
    constexpr float beta  = (STEP == 1) ? -LR  : -2.0f * LR;

    int b       = blockIdx.y;
    int rowTile = blockIdx.x * 128;

    const float* adjB = adj + (size_t)b * N_SZ * N_SZ;
    const float* zB   = (STEP == 1) ? (x + (size_t)b * NC)
                                    : (g_Z + (size_t)b * ZBATCH + NC);
    float*       oB   = g_Z + (size_t)b * ZBATCH + (size_t)STEP * NC;
    const float* xB   = x + (size_t)b * NC;
    const float* cfB  = g_coef + b * N_SZ;

    __shared__ float As[128][36];   // [m][k], pad 4 -> frag LDS conflict-free
    __shared__ float Bs[32][136];   // [k][c], pad 8 -> frag LDS conflict-free

    float acc[4][4][4];
    #pragma unroll
    for (int i = 0; i < 4; i++)
        #pragma unroll
        for (int j = 0; j < 4; j++)
            #pragma unroll
            for (int v = 0; v < 4; v++) acc[i][j][v] = 0.f;

    int tid  = threadIdx.x;
    int lane = tid & 31;
    int warp = tid >> 5;
    int wr = warp >> 2;       // 0..1
    int wc = warp & 3;        // 0..3
    int g  = lane >> 2;       // 0..7
    int tg = lane & 3;        // 0..3

    for (int k0 = 0; k0 < N_SZ; k0 += 32) {
        // stage A tile: adj[rowTile..+127][k0..+31]
        #pragma unroll
        for (int it = 0; it < 4; it++) {
            int r = (tid >> 3) + it * 32;
            int q = (tid & 7) * 4;
            float4 v = *(const float4*)(adjB + (size_t)(rowTile + r) * N_SZ + k0 + q);
            v.x = to_tf32(v.x); v.y = to_tf32(v.y); v.z = to_tf32(v.z); v.w = to_tf32(v.w);
            *(float4*)&As[r][q] = v;
        }
        // stage B tile: z[k0..+31][0..127]
        #pragma unroll
        for (int it = 0; it < 4; it++) {
            int kr = (tid >> 5) + it * 8;
            int q  = (tid & 31) * 4;
            float4 v = *(const float4*)(zB + (size_t)(k0 + kr) * C_SZ + q);
            v.x = to_tf32(v.x); v.y = to_tf32(v.y); v.z = to_tf32(v.z); v.w = to_tf32(v.w);
            *(float4*)&Bs[kr][q] = v;
        }
        __syncthreads();

        #pragma unroll
        for (int ks = 0; ks < 4; ks++) {
            int kb = ks * 8;
            uint32_t bf[4][2];
            #pragma unroll
            for (int ni = 0; ni < 4; ni++) {
                int col = wc * 32 + ni * 8 + g;
                bf[ni][0] = __float_as_uint(Bs[kb + tg][col]);
                bf[ni][1] = __float_as_uint(Bs[kb + tg + 4][col]);
            }
            #pragma unroll
            for (int mi = 0; mi < 4; mi++) {
                int r0 = wr * 64 + mi * 16 + g;
                uint32_t af[4];
                af[0] = __float_as_uint(As[r0    ][kb + tg    ]);
                af[1] = __float_as_uint(As[r0 + 8][kb + tg    ]);
                af[2] = __float_as_uint(As[r0    ][kb + tg + 4]);
                af[3] = __float_as_uint(As[r0 + 8][kb + tg + 4]);
                #pragma unroll
                for (int ni = 0; ni < 4; ni++)
                    mma_tf32(acc[mi][ni], af, bf[ni]);
            }
        }
        __syncthreads();
    }

    // fused elementwise epilogue (exact fp32 on the dominant coef*z term)
    #pragma unroll
    for (int mi = 0; mi < 4; mi++) {
        int r0 = rowTile + wr * 64 + mi * 16 + g;
        int r1 = r0 + 8;
        float cf0 = alpha * cfB[r0];
        float cf1 = alpha * cfB[r1];
        #pragma unroll
        for (int ni = 0; ni < 4; ni++) {
            int c0 = wc * 32 + ni * 8 + tg * 2;
            float2 z0 = *(const float2*)&zB[(size_t)r0 * C_SZ + c0];
            float2 z1 = *(const float2*)&zB[(size_t)r1 * C_SZ + c0];
            float2 o0, o1;
            o0.x = cf0 * z0.x + beta * acc[mi][ni][0];
            o0.y = cf0 * z0.y + beta * acc[mi][ni][1];
            o1.x = cf1 * z1.x + beta * acc[mi][ni][2];
            o1.y = cf1 * z1.y + beta * acc[mi][ni][3];
            if (STEP == 2) {
                float2 x0 = *(const float2*)&xB[(size_t)r0 * C_SZ + c0];
                float2 x1 = *(const float2*)&xB[(size_t)r1 * C_SZ + c0];
                o0.x -= x0.x; o0.y -= x0.y;
                o1.x -= x1.x; o1.y -= x1.y;
            }
            *(float2*)&oB[(size_t)r0 * C_SZ + c0] = o0;
            *(float2*)&oB[(size_t)r1 * C_SZ + c0] = o1;
        }
    }
}

// ---------------------------------------------------------------------------
// Final linear (exact fp32 SIMT; GEMM-dominated output so no tf32 here):
//   out[r][o] = sum_f g_Z_flat[r*384+f] * Wt[f][o],  r in [0,16384)
// ---------------------------------------------------------------------------
__global__ void __launch_bounds__(256)
out_gemm_kernel(float* __restrict__ out) {
    int rowTile = blockIdx.x * 128;

    __shared__ float As[32][132];  // [k][m]
    __shared__ float Bs[32][132];  // [k][o]

    float acc[8][8];
    #pragma unroll
    for (int i = 0; i < 8; i++)
        #pragma unroll
        for (int j = 0; j < 8; j++) acc[i][j] = 0.f;

    int tid = threadIdx.x;
    int tx  = tid & 15;
    int ty  = tid >> 4;

    for (int k0 = 0; k0 < KC; k0 += 32) {
        #pragma unroll
        for (int it = 0; it < 4; it++) {
            int r = (tid >> 3) + it * 32;
            int q = (tid & 7) * 4;
            float4 v = *(const float4*)(g_Z + (size_t)(rowTile + r) * KC + k0 + q);
            As[q + 0][r] = v.x; As[q + 1][r] = v.y;
            As[q + 2][r] = v.z; As[q + 3][r] = v.w;
        }
        #pragma unroll
        for (int it = 0; it < 4; it++) {
            int kr = (tid >> 5) + it * 8;
            int q  = (tid & 31) * 4;
            float4 v = *(const float4*)(g_Wt + (size_t)(k0 + kr) * C_SZ + q);
            *(float4*)&Bs[kr][q] = v;
        }
        __syncthreads();

        #pragma unroll
        for (int kk = 0; kk < 32; kk++) {
            float a[8], bb[8];
            #pragma unroll
            for (int i = 0; i < 8; i++) a[i] = As[kk][ty * 8 + i];
            #pragma unroll
            for (int j = 0; j < 8; j++) bb[j] = Bs[kk][tx * 8 + j];
            #pragma unroll
            for (int i = 0; i < 8; i++)
                #pragma unroll
                for (int j = 0; j < 8; j++)
                    acc[i][j] += a[i] * bb[j];
        }
        __syncthreads();
    }

    #pragma unroll
    for (int i = 0; i < 8; i++) {
        size_t r = (size_t)rowTile + ty * 8 + i;
        #pragma unroll
        for (int j = 0; j < 8; j += 4) {
            float4 v = make_float4(acc[i][j], acc[i][j + 1], acc[i][j + 2], acc[i][j + 3]);
            *(float4*)&out[r * C_SZ + tx * 8 + j] = v;
        }
    }
}

// ---------------------------------------------------------------------------
extern "C" void kernel_launch(void* const* d_in, const int* in_sizes, int n_in,
                              void* d_out, int out_size) {
    const float* x   = nullptr;
    const float* adj = nullptr;
    const float* W   = nullptr;
    for (int i = 0; i < n_in; i++) {
        long long sz = in_sizes[i];
        if (sz == (long long)B_SZ * N_SZ * N_SZ)      adj = (const float*)d_in[i];
        else if (sz == (long long)B_SZ * N_SZ * C_SZ) x   = (const float*)d_in[i];
        else                                          W   = (const float*)d_in[i];
    }
    float* out = (float*)d_out;

    deg_kernel  <<<dim3(N_SZ / 4 / 256, B_SZ), 256>>>(adj);
    copyx_kernel<<<(unsigned)((B_SZ * NC / 4) / 256), 256>>>(x);
    wt_kernel   <<<(KC * C_SZ) / 256, 256>>>(W);

    cheb_mma_kernel<1><<<dim3(N_SZ / 128, B_SZ), 256>>>(adj, x);
    cheb_mma_kernel<2><<<dim3(N_SZ / 128, B_SZ), 256>>>(adj, x);

    out_gemm_kernel<<<(B_SZ * N_SZ) / 128, 256>>>(out);
}

// round 2
// speedup vs baseline: 3.1050x; 3.1050x over previous
#include <cuda_runtime.h>
#include <cstdint>
#include <cstddef>

#define B_SZ 4
#define N_SZ 4096
#define C_SZ 128
#define KCH  3
#define KC   (KCH * C_SZ)                       // 384
#define NC   ((size_t)N_SZ * C_SZ)              // 524288
#define ZBATCH ((size_t)KCH * N_SZ * C_SZ)      // 1572864

static constexpr float LR = 2.0f / (2.0f + 1e-6f);

// Scratch (device globals: no runtime allocation allowed)
__device__ float g_Z[(size_t)B_SZ * KCH * N_SZ * C_SZ];  // [B][K][N][C]  (24 MB)
__device__ float g_part[32 * B_SZ * N_SZ];               // partial column sums
__device__ float g_coef[B_SZ * N_SZ];                    // lr*deg - 1
__device__ float g_Wt[KC * C_SZ];                        // W^T  [384][128]

// ---------------------------------------------------------------------------
// helpers
// ---------------------------------------------------------------------------
__device__ __forceinline__ unsigned smem_u32(const void* p) {
    return (unsigned)__cvta_generic_to_shared(p);
}
__device__ __forceinline__ void cp16(float* dst, const float* src) {
    asm volatile("cp.async.cg.shared.global [%0], [%1], 16;\n"
                 :: "r"(smem_u32(dst)), "l"(src));
}
__device__ __forceinline__ void cp_commit() {
    asm volatile("cp.async.commit_group;\n");
}
template <int Nn>
__device__ __forceinline__ void cp_wait() {
    asm volatile("cp.async.wait_group %0;\n" :: "n"(Nn));
}
// tf32 operand by mantissa truncation (RZ) — HW-independent, 1 LOP per value
__device__ __forceinline__ uint32_t tf32_trunc(float x) {
    return __float_as_uint(x) & 0xFFFFE000u;
}
__device__ __forceinline__ void mma_tf32(float* d, const uint32_t* a, const uint32_t* b) {
    asm volatile(
        "mma.sync.aligned.m16n8k8.row.col.f32.tf32.tf32.f32 "
        "{%0,%1,%2,%3}, {%4,%5,%6,%7}, {%8,%9}, {%0,%1,%2,%3};\n"
        : "+f"(d[0]), "+f"(d[1]), "+f"(d[2]), "+f"(d[3])
        : "r"(a[0]), "r"(a[1]), "r"(a[2]), "r"(a[3]), "r"(b[0]), "r"(b[1]));
}

// ---------------------------------------------------------------------------
// degree: deg[b][m] = sum_n adj[b][n][m].
// Phase 1: 512 blocks, each sums a 128-row chunk for 1024 columns (no atomics).
// Phase 2: deterministic reduce over the 32 chunks; store coef = LR*deg - 1.
// ---------------------------------------------------------------------------
__global__ void deg_part_kernel(const float* __restrict__ adj) {
    int b  = blockIdx.z;
    int rc = blockIdx.y;                                    // 0..31
    int m4 = blockIdx.x * blockDim.x + threadIdx.x;         // 0..1023
    const float* a = adj + (size_t)b * N_SZ * N_SZ
                   + (size_t)rc * 128 * N_SZ + (size_t)m4 * 4;
    float4 s = make_float4(0.f, 0.f, 0.f, 0.f);
    #pragma unroll 8
    for (int n = 0; n < 128; n++) {
        float4 v = *(const float4*)(a + (size_t)n * N_SZ);
        s.x += v.x; s.y += v.y; s.z += v.z; s.w += v.w;
    }
    float* p = g_part + (size_t)rc * (B_SZ * N_SZ) + b * N_SZ + m4 * 4;
    p[0] = s.x; p[1] = s.y; p[2] = s.z; p[3] = s.w;
}

__global__ void deg_reduce_kernel() {
    int i = blockIdx.x * blockDim.x + threadIdx.x;          // 0..16383
    float s = 0.f;
    #pragma unroll
    for (int j = 0; j < 32; j++) s += g_part[(size_t)j * (B_SZ * N_SZ) + i];
    g_coef[i] = LR * s - 1.0f;
}

// ---------------------------------------------------------------------------
// copy x into Z slice 0 (flattened-view layout needs it materialized)
// ---------------------------------------------------------------------------
__global__ void copyx_kernel(const float* __restrict__ x) {
    size_t i   = (size_t)blockIdx.x * blockDim.x + threadIdx.x;  // over float4s
    size_t b   = i / (NC / 4);
    size_t rem = i % (NC / 4);
    float4 v = ((const float4*)x)[i];
    ((float4*)g_Z)[b * (ZBATCH / 4) + rem] = v;
}

// ---------------------------------------------------------------------------
// transpose W [128][384] -> g_Wt [384][128]
// ---------------------------------------------------------------------------
__global__ void wt_kernel(const float* __restrict__ W) {
    int i = blockIdx.x * blockDim.x + threadIdx.x;  // 49152
    int o = i / KC, k = i % KC;
    g_Wt[k * C_SZ + o] = W[i];
}

// ---------------------------------------------------------------------------
// Chebyshev step GEMM, tf32 mma, 2-stage cp.async pipeline.
//   S[n][c] = sum_m adj[b][n][m] * z[b][m][c]
//   STEP 1: out = coef*z - lr*S                    (z = x)
//   STEP 2: out = 2*coef*z - 2*lr*S - x            (z = Z1)
// Block 128x128x32, 8 warps (warp tile 64x32), dynamic smem 70KB (2 stages).
// ---------------------------------------------------------------------------
#define ASTRIDE 36
#define BSTRIDE 136
#define STAGE_FLOATS (128 * ASTRIDE + 32 * BSTRIDE)   // 8960
#define SMEM_BYTES   (2 * STAGE_FLOATS * 4)           // 71680

template <int STEP>
__global__ void __launch_bounds__(256)
cheb_mma_kernel(const float* __restrict__ adj, const float* __restrict__ x) {
    extern __shared__ float sm[];
    constexpr float alpha = (STEP == 1) ? 1.0f : 2.0f;
    constexpr float beta  = (STEP == 1) ? -LR  : -2.0f * LR;

    int b       = blockIdx.y;
    int rowTile = blockIdx.x * 128;

    const float* adjB = adj + (size_t)b * N_SZ * N_SZ;
    const float* zB   = (STEP == 1) ? (x + (size_t)b * NC)
                                    : (g_Z + (size_t)b * ZBATCH + NC);
    float*       oB   = g_Z + (size_t)b * ZBATCH + (size_t)STEP * NC;
    const float* xB   = x + (size_t)b * NC;
    const float* cfB  = g_coef + b * N_SZ;

    int tid  = threadIdx.x;
    int lane = tid & 31;
    int warp = tid >> 5;
    int wr = warp >> 2, wc = warp & 3;
    int g  = lane >> 2, tg = lane & 3;

    float acc[4][4][4];
    #pragma unroll
    for (int i = 0; i < 4; i++)
        #pragma unroll
        for (int j = 0; j < 4; j++)
            #pragma unroll
            for (int v = 0; v < 4; v++) acc[i][j][v] = 0.f;

    auto stage = [&](int s, int k0) {
        float* As = sm + s * STAGE_FLOATS;
        float* Bs = As + 128 * ASTRIDE;
        #pragma unroll
        for (int it = 0; it < 4; it++) {
            int r = (tid >> 3) + it * 32;
            int q = (tid & 7) * 4;
            cp16(As + r * ASTRIDE + q, adjB + (size_t)(rowTile + r) * N_SZ + k0 + q);
        }
        #pragma unroll
        for (int it = 0; it < 4; it++) {
            int kr = (tid >> 5) + it * 8;
            int q  = (tid & 31) * 4;
            cp16(Bs + kr * BSTRIDE + q, zB + (size_t)(k0 + kr) * C_SZ + q);
        }
        cp_commit();
    };

    stage(0, 0);

    for (int kt = 0; kt < 128; kt++) {
        if (kt + 1 < 128) { stage((kt + 1) & 1, (kt + 1) * 32); cp_wait<1>(); }
        else              { cp_wait<0>(); }
        __syncthreads();

        const float* As = sm + (kt & 1) * STAGE_FLOATS;
        const float* Bs = As + 128 * ASTRIDE;

        #pragma unroll
        for (int ks = 0; ks < 4; ks++) {
            int kb = ks * 8;
            uint32_t bf[4][2];
            #pragma unroll
            for (int ni = 0; ni < 4; ni++) {
                int col = wc * 32 + ni * 8 + g;
                bf[ni][0] = tf32_trunc(Bs[(kb + tg) * BSTRIDE + col]);
                bf[ni][1] = tf32_trunc(Bs[(kb + tg + 4) * BSTRIDE + col]);
            }
            #pragma unroll
            for (int mi = 0; mi < 4; mi++) {
                int r0 = wr * 64 + mi * 16 + g;
                uint32_t af[4];
                af[0] = tf32_trunc(As[(r0    ) * ASTRIDE + kb + tg    ]);
                af[1] = tf32_trunc(As[(r0 + 8) * ASTRIDE + kb + tg    ]);
                af[2] = tf32_trunc(As[(r0    ) * ASTRIDE + kb + tg + 4]);
                af[3] = tf32_trunc(As[(r0 + 8) * ASTRIDE + kb + tg + 4]);
                #pragma unroll
                for (int ni = 0; ni < 4; ni++)
                    mma_tf32(acc[mi][ni], af, bf[ni]);
            }
        }
        __syncthreads();
    }

    // fused elementwise epilogue (exact fp32 on the dominant coef*z term)
    #pragma unroll
    for (int mi = 0; mi < 4; mi++) {
        int r0 = rowTile + wr * 64 + mi * 16 + g;
        int r1 = r0 + 8;
        float cf0 = alpha * cfB[r0];
        float cf1 = alpha * cfB[r1];
        #pragma unroll
        for (int ni = 0; ni < 4; ni++) {
            int c0 = wc * 32 + ni * 8 + tg * 2;
            float2 z0 = *(const float2*)&zB[(size_t)r0 * C_SZ + c0];
            float2 z1 = *(const float2*)&zB[(size_t)r1 * C_SZ + c0];
            float2 o0, o1;
            o0.x = cf0 * z0.x + beta * acc[mi][ni][0];
            o0.y = cf0 * z0.y + beta * acc[mi][ni][1];
            o1.x = cf1 * z1.x + beta * acc[mi][ni][2];
            o1.y = cf1 * z1.y + beta * acc[mi][ni][3];
            if (STEP == 2) {
                float2 x0 = *(const float2*)&xB[(size_t)r0 * C_SZ + c0];
                float2 x1 = *(const float2*)&xB[(size_t)r1 * C_SZ + c0];
                o0.x -= x0.x; o0.y -= x0.y;
                o1.x -= x1.x; o1.y -= x1.y;
            }
            *(float2*)&oB[(size_t)r0 * C_SZ + c0] = o0;
            *(float2*)&oB[(size_t)r1 * C_SZ + c0] = o1;
        }
    }
}

// ---------------------------------------------------------------------------
// Final linear via 3xTF32 (hi/lo mantissa split, error ~1e-6):
//   out[r][o] = sum_f Zflat[r][f] * Wt[f][o], r in [0, 16384), f in [0, 384)
// Same 128x128 block / 64x32 warp structure, 2-stage cp.async, 12 k-tiles.
// ---------------------------------------------------------------------------
__global__ void __launch_bounds__(256)
out_gemm_kernel(float* __restrict__ out) {
    extern __shared__ float sm[];
    int rowTile = blockIdx.x * 128;

    int tid  = threadIdx.x;
    int lane = tid & 31;
    int warp = tid >> 5;
    int wr = warp >> 2, wc = warp & 3;
    int g  = lane >> 2, tg = lane & 3;

    float acc[4][4][4];
    #pragma unroll
    for (int i = 0; i < 4; i++)
        #pragma unroll
        for (int j = 0; j < 4; j++)
            #pragma unroll
            for (int v = 0; v < 4; v++) acc[i][j][v] = 0.f;

    auto stage = [&](int s, int k0) {
        float* As = sm + s * STAGE_FLOATS;
        float* Bs = As + 128 * ASTRIDE;
        #pragma unroll
        for (int it = 0; it < 4; it++) {
            int r = (tid >> 3) + it * 32;
            int q = (tid & 7) * 4;
            cp16(As + r * ASTRIDE + q, g_Z + (size_t)(rowTile + r) * KC + k0 + q);
        }
        #pragma unroll
        for (int it = 0; it < 4; it++) {
            int kr = (tid >> 5) + it * 8;
            int q  = (tid & 31) * 4;
            cp16(Bs + kr * BSTRIDE + q, g_Wt + (size_t)(k0 + kr) * C_SZ + q);
        }
        cp_commit();
    };

    stage(0, 0);

    for (int kt = 0; kt < 12; kt++) {
        if (kt + 1 < 12) { stage((kt + 1) & 1, (kt + 1) * 32); cp_wait<1>(); }
        else             { cp_wait<0>(); }
        __syncthreads();

        const float* As = sm + (kt & 1) * STAGE_FLOATS;
        const float* Bs = As + 128 * ASTRIDE;

        #pragma unroll
        for (int ks = 0; ks < 4; ks++) {
            int kb = ks * 8;
            uint32_t bh[4][2], bl[4][2];
            #pragma unroll
            for (int ni = 0; ni < 4; ni++) {
                int col = wc * 32 + ni * 8 + g;
                float v0 = Bs[(kb + tg) * BSTRIDE + col];
                float v1 = Bs[(kb + tg + 4) * BSTRIDE + col];
                bh[ni][0] = tf32_trunc(v0);
                bh[ni][1] = tf32_trunc(v1);
                bl[ni][0] = tf32_trunc(v0 - __uint_as_float(bh[ni][0]));
                bl[ni][1] = tf32_trunc(v1 - __uint_as_float(bh[ni][1]));
            }
            #pragma unroll
            for (int mi = 0; mi < 4; mi++) {
                int r0 = wr * 64 + mi * 16 + g;
                float a0 = As[(r0    ) * ASTRIDE + kb + tg    ];
                float a1 = As[(r0 + 8) * ASTRIDE + kb + tg    ];
                float a2 = As[(r0    ) * ASTRIDE + kb + tg + 4];
                float a3 = As[(r0 + 8) * ASTRIDE + kb + tg + 4];
                uint32_t ah[4], al[4];
                ah[0] = tf32_trunc(a0); ah[1] = tf32_trunc(a1);
                ah[2] = tf32_trunc(a2); ah[3] = tf32_trunc(a3);
                al[0] = tf32_trunc(a0 - __uint_as_float(ah[0]));
                al[1] = tf32_trunc(a1 - __uint_as_float(ah[1]));
                al[2] = tf32_trunc(a2 - __uint_as_float(ah[2]));
                al[3] = tf32_trunc(a3 - __uint_as_float(ah[3]));
                #pragma unroll
                for (int ni = 0; ni < 4; ni++) {
                    mma_tf32(acc[mi][ni], ah, bh[ni]);   // hi*hi
                    mma_tf32(acc[mi][ni], ah, bl[ni]);   // hi*lo
                    mma_tf32(acc[mi][ni], al, bh[ni]);   // lo*hi
                }
            }
        }
        __syncthreads();
    }

    #pragma unroll
    for (int mi = 0; mi < 4; mi++) {
        size_t r0 = (size_t)rowTile + wr * 64 + mi * 16 + g;
        size_t r1 = r0 + 8;
        #pragma unroll
        for (int ni = 0; ni < 4; ni++) {
            int c0 = wc * 32 + ni * 8 + tg * 2;
            *(float2*)&out[r0 * C_SZ + c0] = make_float2(acc[mi][ni][0], acc[mi][ni][1]);
            *(float2*)&out[r1 * C_SZ + c0] = make_float2(acc[mi][ni][2], acc[mi][ni][3]);
        }
    }
}

// ---------------------------------------------------------------------------
extern "C" void kernel_launch(void* const* d_in, const int* in_sizes, int n_in,
                              void* d_out, int out_size) {
    const float* x   = nullptr;
    const float* adj = nullptr;
    const float* W   = nullptr;
    for (int i = 0; i < n_in; i++) {
        long long sz = in_sizes[i];
        if (sz == (long long)B_SZ * N_SZ * N_SZ)      adj = (const float*)d_in[i];
        else if (sz == (long long)B_SZ * N_SZ * C_SZ) x   = (const float*)d_in[i];
        else                                          W   = (const float*)d_in[i];
    }
    float* out = (float*)d_out;

    cudaFuncSetAttribute(cheb_mma_kernel<1>,
                         cudaFuncAttributeMaxDynamicSharedMemorySize, SMEM_BYTES);
    cudaFuncSetAttribute(cheb_mma_kernel<2>,
                         cudaFuncAttributeMaxDynamicSharedMemorySize, SMEM_BYTES);
    cudaFuncSetAttribute(out_gemm_kernel,
                         cudaFuncAttributeMaxDynamicSharedMemorySize, SMEM_BYTES);

    deg_part_kernel  <<<dim3(4, 32, B_SZ), 256>>>(adj);
    deg_reduce_kernel<<<(B_SZ * N_SZ) / 256, 256>>>();
    copyx_kernel     <<<(unsigned)((B_SZ * NC / 4) / 256), 256>>>(x);
    wt_kernel        <<<(KC * C_SZ) / 256, 256>>>(W);

    cheb_mma_kernel<1><<<dim3(N_SZ / 128, B_SZ), 256, SMEM_BYTES>>>(adj, x);
    cheb_mma_kernel<2><<<dim3(N_SZ / 128, B_SZ), 256, SMEM_BYTES>>>(adj, x);

    out_gemm_kernel<<<(B_SZ * N_SZ) / 128, 256, SMEM_BYTES>>>(out);
}

// round 7
// speedup vs baseline: 3.3174x; 1.0684x over previous
#include <cuda_runtime.h>
#include <cstdint>
#include <cstddef>

#define B_SZ 4
#define N_SZ 4096
#define C_SZ 128
#define KCH  3
#define KC   (KCH * C_SZ)                       // 384
#define NC   ((size_t)N_SZ * C_SZ)              // 524288
#define ZBATCH ((size_t)KCH * N_SZ * C_SZ)      // 1572864

static constexpr float LR = 2.0f / (2.0f + 1e-6f);

// Scratch (device globals: no runtime allocation allowed)
__device__ float g_Z[(size_t)B_SZ * KCH * N_SZ * C_SZ];  // [B][K][N][C]  (24 MB)
__device__ float g_part[32 * B_SZ * N_SZ];               // partial column sums
__device__ float g_coef[B_SZ * N_SZ];                    // lr*deg - 1
__device__ float g_Wt[KC * C_SZ];                        // W^T  [384][128]

// ---------------------------------------------------------------------------
// helpers
// ---------------------------------------------------------------------------
__device__ __forceinline__ unsigned smem_u32(const void* p) {
    return (unsigned)__cvta_generic_to_shared(p);
}
__device__ __forceinline__ void cp16(float* dst, const float* src) {
    asm volatile("cp.async.cg.shared.global [%0], [%1], 16;\n"
                 :: "r"(smem_u32(dst)), "l"(src));
}
__device__ __forceinline__ void cp_commit() { asm volatile("cp.async.commit_group;\n"); }
template <int Nn>
__device__ __forceinline__ void cp_wait() {
    asm volatile("cp.async.wait_group %0;\n" :: "n"(Nn));
}
// tf32 operand by mantissa truncation (RZ) — 1 LOP per value
__device__ __forceinline__ uint32_t tf32_trunc(float x) {
    return __float_as_uint(x) & 0xFFFFE000u;
}
__device__ __forceinline__ void mma_tf32(float* d, const uint32_t* a, const uint32_t* b) {
    asm volatile(
        "mma.sync.aligned.m16n8k8.row.col.f32.tf32.tf32.f32 "
        "{%0,%1,%2,%3}, {%4,%5,%6,%7}, {%8,%9}, {%0,%1,%2,%3};\n"
        : "+f"(d[0]), "+f"(d[1]), "+f"(d[2]), "+f"(d[3])
        : "r"(a[0]), "r"(a[1]), "r"(a[2]), "r"(a[3]), "r"(b[0]), "r"(b[1]));
}

// ---------------------------------------------------------------------------
// degree: deg[b][m] = sum_n adj[b][n][m]  (column sums), 2-phase, no atomics
// ---------------------------------------------------------------------------
__global__ void deg_part_kernel(const float* __restrict__ adj) {
    int b  = blockIdx.z;
    int rc = blockIdx.y;                                    // 0..31
    int m4 = blockIdx.x * blockDim.x + threadIdx.x;         // 0..1023
    const float* a = adj + (size_t)b * N_SZ * N_SZ
                   + (size_t)rc * 128 * N_SZ + (size_t)m4 * 4;
    float4 s = make_float4(0.f, 0.f, 0.f, 0.f);
    #pragma unroll 8
    for (int n = 0; n < 128; n++) {
        float4 v = *(const float4*)(a + (size_t)n * N_SZ);
        s.x += v.x; s.y += v.y; s.z += v.z; s.w += v.w;
    }
    float* p = g_part + (size_t)rc * (B_SZ * N_SZ) + b * N_SZ + m4 * 4;
    p[0] = s.x; p[1] = s.y; p[2] = s.z; p[3] = s.w;
}

__global__ void deg_reduce_kernel() {
    int i = blockIdx.x * blockDim.x + threadIdx.x;          // 0..16383
    float s = 0.f;
    #pragma unroll
    for (int j = 0; j < 32; j++) s += g_part[(size_t)j * (B_SZ * N_SZ) + i];
    g_coef[i] = LR * s - 1.0f;
}

// ---------------------------------------------------------------------------
// copy x into Z slice 0 (flattened-view layout needs it materialized)
// ---------------------------------------------------------------------------
__global__ void copyx_kernel(const float* __restrict__ x) {
    size_t i   = (size_t)blockIdx.x * blockDim.x + threadIdx.x;  // over float4s
    size_t b   = i / (NC / 4);
    size_t rem = i % (NC / 4);
    float4 v = ((const float4*)x)[i];
    ((float4*)g_Z)[b * (ZBATCH / 4) + rem] = v;
}

// ---------------------------------------------------------------------------
// transpose W [128][384] -> g_Wt [384][128]
// ---------------------------------------------------------------------------
__global__ void wt_kernel(const float* __restrict__ W) {
    int i = blockIdx.x * blockDim.x + threadIdx.x;  // 49152
    int o = i / KC, k = i % KC;
    g_Wt[k * C_SZ + o] = W[i];
}

// ---------------------------------------------------------------------------
// Chebyshev step GEMM, tf32 mma.sync, 3-stage cp.async pipeline with a single
// __syncthreads per k-iteration (distance-2 prefetch; the top-of-loop barrier
// orders prefetch into (kt+2)%3 == (kt-1)%3 against last iteration's reads).
//   S[n][c] = sum_m adj[b][n][m] * z[b][m][c]
//   STEP 1: out = coef*z - lr*S                    (z = x)
//   STEP 2: out = 2*coef*z - 2*lr*S - x            (z = Z1)
// Block 128x128x32, 8 warps (warp tile 64x32), 105KB dynamic smem (3 stages).
// ---------------------------------------------------------------------------
#define ASTRIDE 36
#define BSTRIDE 136
#define STAGE_FLOATS (128 * ASTRIDE + 32 * BSTRIDE)   // 8960
#define STG 3
#define SMEM_BYTES   (STG * STAGE_FLOATS * 4)         // 107520

template <int STEP>
__global__ void __launch_bounds__(256, 1)
cheb_mma_kernel(const float* __restrict__ adj, const float* __restrict__ x) {
    extern __shared__ float sm[];
    constexpr float alpha = (STEP == 1) ? 1.0f : 2.0f;
    constexpr float beta  = (STEP == 1) ? -LR  : -2.0f * LR;

    int b       = blockIdx.y;
    int rowTile = blockIdx.x * 128;

    const float* adjB = adj + (size_t)b * N_SZ * N_SZ;
    const float* zB   = (STEP == 1) ? (x + (size_t)b * NC)
                                    : (g_Z + (size_t)b * ZBATCH + NC);
    float*       oB   = g_Z + (size_t)b * ZBATCH + (size_t)STEP * NC;
    const float* xB   = x + (size_t)b * NC;
    const float* cfB  = g_coef + b * N_SZ;

    int tid  = threadIdx.x;
    int lane = tid & 31;
    int warp = tid >> 5;
    int wr = warp >> 2, wc = warp & 3;
    int g  = lane >> 2, tg = lane & 3;

    float acc[4][4][4];
    #pragma unroll
    for (int i = 0; i < 4; i++)
        #pragma unroll
        for (int j = 0; j < 4; j++)
            #pragma unroll
            for (int v = 0; v < 4; v++) acc[i][j][v] = 0.f;

    auto stage = [&](int t) {
        float* As = sm + (t % STG) * STAGE_FLOATS;
        float* Bs = As + 128 * ASTRIDE;
        int k0 = t * 32;
        #pragma unroll
        for (int it = 0; it < 4; it++) {
            int r = (tid >> 3) + it * 32;
            int q = (tid & 7) * 4;
            cp16(As + r * ASTRIDE + q, adjB + (size_t)(rowTile + r) * N_SZ + k0 + q);
        }
        #pragma unroll
        for (int it = 0; it < 4; it++) {
            int kr = (tid >> 5) + it * 8;
            int q  = (tid & 31) * 4;
            cp16(Bs + kr * BSTRIDE + q, zB + (size_t)(k0 + kr) * C_SZ + q);
        }
        cp_commit();
    };

    stage(0); stage(1);

    for (int kt = 0; kt < 128; kt++) {
        cp_wait<1>();          // retire group kt (2 groups in flight at entry)
        __syncthreads();       // all warps see stage kt; orders vs prefetch below

        const float* As = sm + (kt % STG) * STAGE_FLOATS;
        const float* Bs = As + 128 * ASTRIDE;

        #pragma unroll
        for (int ks = 0; ks < 4; ks++) {
            int kb = ks * 8;
            uint32_t bf[4][2];
            #pragma unroll
            for (int ni = 0; ni < 4; ni++) {
                int col = wc * 32 + ni * 8 + g;
                bf[ni][0] = tf32_trunc(Bs[(kb + tg) * BSTRIDE + col]);
                bf[ni][1] = tf32_trunc(Bs[(kb + tg + 4) * BSTRIDE + col]);
            }
            #pragma unroll
            for (int mi = 0; mi < 4; mi++) {
                int r0 = wr * 64 + mi * 16 + g;
                uint32_t af[4];
                af[0] = tf32_trunc(As[(r0    ) * ASTRIDE + kb + tg    ]);
                af[1] = tf32_trunc(As[(r0 + 8) * ASTRIDE + kb + tg    ]);
                af[2] = tf32_trunc(As[(r0    ) * ASTRIDE + kb + tg + 4]);
                af[3] = tf32_trunc(As[(r0 + 8) * ASTRIDE + kb + tg + 4]);
                #pragma unroll
                for (int ni = 0; ni < 4; ni++)
                    mma_tf32(acc[mi][ni], af, bf[ni]);
            }
        }

        if (kt + 2 < 128) stage(kt + 2);
        else              cp_commit();   // empty group keeps wait<1> exact
    }

    // fused elementwise epilogue (exact fp32 on the dominant coef*z term)
    #pragma unroll
    for (int mi = 0; mi < 4; mi++) {
        int r0 = rowTile + wr * 64 + mi * 16 + g;
        int r1 = r0 + 8;
        float cf0 = alpha * cfB[r0];
        float cf1 = alpha * cfB[r1];
        #pragma unroll
        for (int ni = 0; ni < 4; ni++) {
            int c0 = wc * 32 + ni * 8 + tg * 2;
            float2 z0 = *(const float2*)&zB[(size_t)r0 * C_SZ + c0];
            float2 z1 = *(const float2*)&zB[(size_t)r1 * C_SZ + c0];
            float2 o0, o1;
            o0.x = cf0 * z0.x + beta * acc[mi][ni][0];
            o0.y = cf0 * z0.y + beta * acc[mi][ni][1];
            o1.x = cf1 * z1.x + beta * acc[mi][ni][2];
            o1.y = cf1 * z1.y + beta * acc[mi][ni][3];
            if (STEP == 2) {
                float2 x0 = *(const float2*)&xB[(size_t)r0 * C_SZ + c0];
                float2 x1 = *(const float2*)&xB[(size_t)r1 * C_SZ + c0];
                o0.x -= x0.x; o0.y -= x0.y;
                o1.x -= x1.x; o1.y -= x1.y;
            }
            *(float2*)&oB[(size_t)r0 * C_SZ + c0] = o0;
            *(float2*)&oB[(size_t)r1 * C_SZ + c0] = o1;
        }
    }
}

// ---------------------------------------------------------------------------
// Final linear via 3xTF32 (hi/lo mantissa split, error ~1e-6):
//   out[r][o] = sum_f Zflat[r][f] * Wt[f][o], r in [0, 16384), f in [0, 384)
// Same structure: 3-stage cp.async, single sync per k-iter, 12 k-tiles.
// ---------------------------------------------------------------------------
__global__ void __launch_bounds__(256, 1)
out_gemm_kernel(float* __restrict__ out) {
    extern __shared__ float sm[];
    int rowTile = blockIdx.x * 128;

    int tid  = threadIdx.x;
    int lane = tid & 31;
    int warp = tid >> 5;
    int wr = warp >> 2, wc = warp & 3;
    int g  = lane >> 2, tg = lane & 3;

    float acc[4][4][4];
    #pragma unroll
    for (int i = 0; i < 4; i++)
        #pragma unroll
        for (int j = 0; j < 4; j++)
            #pragma unroll
            for (int v = 0; v < 4; v++) acc[i][j][v] = 0.f;

    auto stage = [&](int t) {
        float* As = sm + (t % STG) * STAGE_FLOATS;
        float* Bs = As + 128 * ASTRIDE;
        int k0 = t * 32;
        #pragma unroll
        for (int it = 0; it < 4; it++) {
            int r = (tid >> 3) + it * 32;
            int q = (tid & 7) * 4;
            cp16(As + r * ASTRIDE + q, g_Z + (size_t)(rowTile + r) * KC + k0 + q);
        }
        #pragma unroll
        for (int it = 0; it < 4; it++) {
            int kr = (tid >> 5) + it * 8;
            int q  = (tid & 31) * 4;
            cp16(Bs + kr * BSTRIDE + q, g_Wt + (size_t)(k0 + kr) * C_SZ + q);
        }
        cp_commit();
    };

    stage(0); stage(1);

    for (int kt = 0; kt < 12; kt++) {
        cp_wait<1>();
        __syncthreads();

        const float* As = sm + (kt % STG) * STAGE_FLOATS;
        const float* Bs = As + 128 * ASTRIDE;

        #pragma unroll
        for (int ks = 0; ks < 4; ks++) {
            int kb = ks * 8;
            uint32_t bh[4][2], bl[4][2];
            #pragma unroll
            for (int ni = 0; ni < 4; ni++) {
                int col = wc * 32 + ni * 8 + g;
                float v0 = Bs[(kb + tg) * BSTRIDE + col];
                float v1 = Bs[(kb + tg + 4) * BSTRIDE + col];
                bh[ni][0] = tf32_trunc(v0);
                bh[ni][1] = tf32_trunc(v1);
                bl[ni][0] = tf32_trunc(v0 - __uint_as_float(bh[ni][0]));
                bl[ni][1] = tf32_trunc(v1 - __uint_as_float(bh[ni][1]));
            }
            #pragma unroll
            for (int mi = 0; mi < 4; mi++) {
                int r0 = wr * 64 + mi * 16 + g;
                float a0 = As[(r0    ) * ASTRIDE + kb + tg    ];
                float a1 = As[(r0 + 8) * ASTRIDE + kb + tg    ];
                float a2 = As[(r0    ) * ASTRIDE + kb + tg + 4];
                float a3 = As[(r0 + 8) * ASTRIDE + kb + tg + 4];
                uint32_t ah[4], al[4];
                ah[0] = tf32_trunc(a0); ah[1] = tf32_trunc(a1);
                ah[2] = tf32_trunc(a2); ah[3] = tf32_trunc(a3);
                al[0] = tf32_trunc(a0 - __uint_as_float(ah[0]));
                al[1] = tf32_trunc(a1 - __uint_as_float(ah[1]));
                al[2] = tf32_trunc(a2 - __uint_as_float(ah[2]));
                al[3] = tf32_trunc(a3 - __uint_as_float(ah[3]));
                #pragma unroll
                for (int ni = 0; ni < 4; ni++) {
                    mma_tf32(acc[mi][ni], ah, bh[ni]);   // hi*hi
                    mma_tf32(acc[mi][ni], ah, bl[ni]);   // hi*lo
                    mma_tf32(acc[mi][ni], al, bh[ni]);   // lo*hi
                }
            }
        }

        if (kt + 2 < 12) stage(kt + 2);
        else             cp_commit();
    }

    #pragma unroll
    for (int mi = 0; mi < 4; mi++) {
        size_t r0 = (size_t)rowTile + wr * 64 + mi * 16 + g;
        size_t r1 = r0 + 8;
        #pragma unroll
        for (int ni = 0; ni < 4; ni++) {
            int c0 = wc * 32 + ni * 8 + tg * 2;
            *(float2*)&out[r0 * C_SZ + c0] = make_float2(acc[mi][ni][0], acc[mi][ni][1]);
            *(float2*)&out[r1 * C_SZ + c0] = make_float2(acc[mi][ni][2], acc[mi][ni][3]);
        }
    }
}

// ---------------------------------------------------------------------------
extern "C" void kernel_launch(void* const* d_in, const int* in_sizes, int n_in,
                              void* d_out, int out_size) {
    const float* x   = nullptr;
    const float* adj = nullptr;
    const float* W   = nullptr;
    for (int i = 0; i < n_in; i++) {
        long long sz = in_sizes[i];
        if (sz == (long long)B_SZ * N_SZ * N_SZ)      adj = (const float*)d_in[i];
        else if (sz == (long long)B_SZ * N_SZ * C_SZ) x   = (const float*)d_in[i];
        else                                          W   = (const float*)d_in[i];
    }
    float* out = (float*)d_out;

    cudaFuncSetAttribute(cheb_mma_kernel<1>,
                         cudaFuncAttributeMaxDynamicSharedMemorySize, SMEM_BYTES);
    cudaFuncSetAttribute(cheb_mma_kernel<2>,
                         cudaFuncAttributeMaxDynamicSharedMemorySize, SMEM_BYTES);
    cudaFuncSetAttribute(out_gemm_kernel,
                         cudaFuncAttributeMaxDynamicSharedMemorySize, SMEM_BYTES);

    deg_part_kernel  <<<dim3(4, 32, B_SZ), 256>>>(adj);
    deg_reduce_kernel<<<(B_SZ * N_SZ) / 256, 256>>>();
    copyx_kernel     <<<(unsigned)((B_SZ * NC / 4) / 256), 256>>>(x);
    wt_kernel        <<<(KC * C_SZ) / 256, 256>>>(W);

    cheb_mma_kernel<1><<<dim3(N_SZ / 128, B_SZ), 256, SMEM_BYTES>>>(adj, x);
    cheb_mma_kernel<2><<<dim3(N_SZ / 128, B_SZ), 256, SMEM_BYTES>>>(adj, x);

    out_gemm_kernel<<<(B_SZ * N_SZ) / 128, 256, SMEM_BYTES>>>(out);
}

// round 8
// speedup vs baseline: 3.4722x; 1.0467x over previous
#include <cuda_runtime.h>
#include <cstdint>
#include <cstddef>

#define B_SZ 4
#define N_SZ 4096
#define C_SZ 128
#define KCH  3
#define KC   (KCH * C_SZ)                       // 384
#define NC   ((size_t)N_SZ * C_SZ)              // 524288
#define ZBATCH ((size_t)KCH * N_SZ * C_SZ)      // 1572864

static constexpr float LR = 2.0f / (2.0f + 1e-6f);

// Scratch (device globals: no runtime allocation allowed)
__device__ float g_Z[(size_t)B_SZ * KCH * N_SZ * C_SZ];   // [B][K][N][C]  (24 MB)
__device__ float g_part2[(size_t)B_SZ * 32 * 8 * N_SZ];   // per-(CTA,warp) colsum partials (16 MB)
__device__ float g_coef[B_SZ * N_SZ];                     // lr*deg - 1

// ---------------------------------------------------------------------------
// helpers
// ---------------------------------------------------------------------------
__device__ __forceinline__ unsigned smem_u32(const void* p) {
    return (unsigned)__cvta_generic_to_shared(p);
}
__device__ __forceinline__ void cp16(float* dst, const float* src) {
    asm volatile("cp.async.cg.shared.global [%0], [%1], 16;\n"
                 :: "r"(smem_u32(dst)), "l"(src));
}
__device__ __forceinline__ void cp_commit() { asm volatile("cp.async.commit_group;\n"); }
template <int Nn>
__device__ __forceinline__ void cp_wait() {
    asm volatile("cp.async.wait_group %0;\n" :: "n"(Nn));
}
// tf32 operand by mantissa truncation (RZ) — 1 LOP per value
__device__ __forceinline__ uint32_t tf32_trunc(float x) {
    return __float_as_uint(x) & 0xFFFFE000u;
}
__device__ __forceinline__ void mma_tf32(float* d, const uint32_t* a, const uint32_t* b) {
    asm volatile(
        "mma.sync.aligned.m16n8k8.row.col.f32.tf32.tf32.f32 "
        "{%0,%1,%2,%3}, {%4,%5,%6,%7}, {%8,%9}, {%0,%1,%2,%3};\n"
        : "+f"(d[0]), "+f"(d[1]), "+f"(d[2]), "+f"(d[3])
        : "r"(a[0]), "r"(a[1]), "r"(a[2]), "r"(a[3]), "r"(b[0]), "r"(b[1]));
}

#define ASTRIDE 36
#define BSTRIDE 136
#define STAGE_FLOATS (128 * ASTRIDE + 32 * BSTRIDE)   // 8960
#define STG 3
#define SMEM_BYTES   (STG * STAGE_FLOATS * 4)         // 107520

// ---------------------------------------------------------------------------
// Chebyshev STEP 1 GEMM + fused degree partial column sums.
//   Writes  g_Z slice1 = -LR * (adj @ x)     (combine1 finishes Z1)
//   Writes  g_part2[b][rowChunk][warp][m] = sum of this warp's 16 adj rows.
// Pipeline: 3-stage cp.async ring, single __syncthreads per k-iter.
// ---------------------------------------------------------------------------
__global__ void __launch_bounds__(256, 1)
cheb1_mma_kernel(const float* __restrict__ adj, const float* __restrict__ x) {
    extern __shared__ float sm[];

    int b       = blockIdx.y;
    int rowTile = blockIdx.x * 128;

    const float* adjB = adj + (size_t)b * N_SZ * N_SZ;
    const float* zB   = x + (size_t)b * NC;
    float*       oB   = g_Z + (size_t)b * ZBATCH + NC;      // slice 1
    float*       prt  = g_part2 + (((size_t)b * 32 + blockIdx.x) * 8) * N_SZ;

    int tid  = threadIdx.x;
    int lane = tid & 31;
    int warp = tid >> 5;
    int wr = warp >> 2, wc = warp & 3;
    int g  = lane >> 2, tg = lane & 3;

    float acc[4][4][4];
    #pragma unroll
    for (int i = 0; i < 4; i++)
        #pragma unroll
        for (int j = 0; j < 4; j++)
            #pragma unroll
            for (int v = 0; v < 4; v++) acc[i][j][v] = 0.f;

    auto stage = [&](int t) {
        float* As = sm + (t % STG) * STAGE_FLOATS;
        float* Bs = As + 128 * ASTRIDE;
        int k0 = t * 32;
        #pragma unroll
        for (int it = 0; it < 4; it++) {
            int r = (tid >> 3) + it * 32;
            int q = (tid & 7) * 4;
            cp16(As + r * ASTRIDE + q, adjB + (size_t)(rowTile + r) * N_SZ + k0 + q);
        }
        #pragma unroll
        for (int it = 0; it < 4; it++) {
            int kr = (tid >> 5) + it * 8;
            int q  = (tid & 31) * 4;
            cp16(Bs + kr * BSTRIDE + q, zB + (size_t)(k0 + kr) * C_SZ + q);
        }
        cp_commit();
    };

    stage(0); stage(1);

    for (int kt = 0; kt < 128; kt++) {
        cp_wait<1>();
        __syncthreads();

        const float* As = sm + (kt % STG) * STAGE_FLOATS;
        const float* Bs = As + 128 * ASTRIDE;

        #pragma unroll
        for (int ks = 0; ks < 4; ks++) {
            int kb = ks * 8;
            uint32_t bf[4][2];
            #pragma unroll
            for (int ni = 0; ni < 4; ni++) {
                int col = wc * 32 + ni * 8 + g;
                bf[ni][0] = tf32_trunc(Bs[(kb + tg) * BSTRIDE + col]);
                bf[ni][1] = tf32_trunc(Bs[(kb + tg + 4) * BSTRIDE + col]);
            }
            #pragma unroll
            for (int mi = 0; mi < 4; mi++) {
                int r0 = wr * 64 + mi * 16 + g;
                uint32_t af[4];
                af[0] = tf32_trunc(As[(r0    ) * ASTRIDE + kb + tg    ]);
                af[1] = tf32_trunc(As[(r0 + 8) * ASTRIDE + kb + tg    ]);
                af[2] = tf32_trunc(As[(r0    ) * ASTRIDE + kb + tg + 4]);
                af[3] = tf32_trunc(As[(r0 + 8) * ASTRIDE + kb + tg + 4]);
                #pragma unroll
                for (int ni = 0; ni < 4; ni++)
                    mma_tf32(acc[mi][ni], af, bf[ni]);
            }
        }

        // fused degree partials: warp sums its 16 rows of col=lane (conflict-free)
        {
            float cs = 0.f;
            #pragma unroll
            for (int r = 0; r < 16; r++)
                cs += As[(warp * 16 + r) * ASTRIDE + lane];
            prt[(size_t)warp * N_SZ + kt * 32 + lane] = cs;
        }

        if (kt + 2 < 128) stage(kt + 2);
        else              cp_commit();
    }

    // epilogue: store -LR * S (combine1 adds coef*x)
    #pragma unroll
    for (int mi = 0; mi < 4; mi++) {
        int r0 = rowTile + wr * 64 + mi * 16 + g;
        int r1 = r0 + 8;
        #pragma unroll
        for (int ni = 0; ni < 4; ni++) {
            int c0 = wc * 32 + ni * 8 + tg * 2;
            *(float2*)&oB[(size_t)r0 * C_SZ + c0] =
                make_float2(-LR * acc[mi][ni][0], -LR * acc[mi][ni][1]);
            *(float2*)&oB[(size_t)r1 * C_SZ + c0] =
                make_float2(-LR * acc[mi][ni][2], -LR * acc[mi][ni][3]);
        }
    }
}

// ---------------------------------------------------------------------------
// coef[b][m] = LR * (sum of 256 partials) - 1
// ---------------------------------------------------------------------------
__global__ void deg_reduce_kernel() {
    int i = blockIdx.x * blockDim.x + threadIdx.x;   // 0..16383 = b*4096 + m
    int b = i >> 12, m = i & 4095;
    float s = 0.f;
    #pragma unroll 8
    for (int j = 0; j < 256; j++)
        s += g_part2[((size_t)b * 256 + j) * N_SZ + m];
    g_coef[i] = LR * s - 1.0f;
}

// ---------------------------------------------------------------------------
// combine1: slice0 = x;  slice1 = coef*x + slice1   (slice1 held -LR*S)
// ---------------------------------------------------------------------------
__global__ void combine1_kernel(const float* __restrict__ x) {
    size_t i   = (size_t)blockIdx.x * blockDim.x + threadIdx.x;  // float4 index
    size_t b   = i / (NC / 4);
    size_t rem = i % (NC / 4);
    size_t row = rem >> 5;                                       // C/4 = 32
    float cf = g_coef[b * N_SZ + row];
    float4 xv = ((const float4*)x)[i];
    float4* z0 = (float4*)g_Z + b * (ZBATCH / 4) + rem;
    float4* z1 = z0 + NC / 4;
    float4 s1 = *z1;
    s1.x += cf * xv.x; s1.y += cf * xv.y; s1.z += cf * xv.z; s1.w += cf * xv.w;
    *z0 = xv;
    *z1 = s1;
}

// ---------------------------------------------------------------------------
// Chebyshev STEP 2 GEMM with fused epilogue (coef available):
//   out = 2*coef*z - 2*lr*(adj@z) - x,   z = Z1
// ---------------------------------------------------------------------------
__global__ void __launch_bounds__(256, 1)
cheb2_mma_kernel(const float* __restrict__ adj, const float* __restrict__ x) {
    extern __shared__ float sm[];
    constexpr float alpha = 2.0f;
    constexpr float beta  = -2.0f * LR;

    int b       = blockIdx.y;
    int rowTile = blockIdx.x * 128;

    const float* adjB = adj + (size_t)b * N_SZ * N_SZ;
    const float* zB   = g_Z + (size_t)b * ZBATCH + NC;       // slice 1
    float*       oB   = g_Z + (size_t)b * ZBATCH + 2 * NC;   // slice 2
    const float* xB   = x + (size_t)b * NC;
    const float* cfB  = g_coef + b * N_SZ;

    int tid  = threadIdx.x;
    int lane = tid & 31;
    int warp = tid >> 5;
    int wr = warp >> 2, wc = warp & 3;
    int g  = lane >> 2, tg = lane & 3;

    float acc[4][4][4];
    #pragma unroll
    for (int i = 0; i < 4; i++)
        #pragma unroll
        for (int j = 0; j < 4; j++)
            #pragma unroll
            for (int v = 0; v < 4; v++) acc[i][j][v] = 0.f;

    auto stage = [&](int t) {
        float* As = sm + (t % STG) * STAGE_FLOATS;
        float* Bs = As + 128 * ASTRIDE;
        int k0 = t * 32;
        #pragma unroll
        for (int it = 0; it < 4; it++) {
            int r = (tid >> 3) + it * 32;
            int q = (tid & 7) * 4;
            cp16(As + r * ASTRIDE + q, adjB + (size_t)(rowTile + r) * N_SZ + k0 + q);
        }
        #pragma unroll
        for (int it = 0; it < 4; it++) {
            int kr = (tid >> 5) + it * 8;
            int q  = (tid & 31) * 4;
            cp16(Bs + kr * BSTRIDE + q, zB + (size_t)(k0 + kr) * C_SZ + q);
        }
        cp_commit();
    };

    stage(0); stage(1);

    for (int kt = 0; kt < 128; kt++) {
        cp_wait<1>();
        __syncthreads();

        const float* As = sm + (kt % STG) * STAGE_FLOATS;
        const float* Bs = As + 128 * ASTRIDE;

        #pragma unroll
        for (int ks = 0; ks < 4; ks++) {
            int kb = ks * 8;
            uint32_t bf[4][2];
            #pragma unroll
            for (int ni = 0; ni < 4; ni++) {
                int col = wc * 32 + ni * 8 + g;
                bf[ni][0] = tf32_trunc(Bs[(kb + tg) * BSTRIDE + col]);
                bf[ni][1] = tf32_trunc(Bs[(kb + tg + 4) * BSTRIDE + col]);
            }
            #pragma unroll
            for (int mi = 0; mi < 4; mi++) {
                int r0 = wr * 64 + mi * 16 + g;
                uint32_t af[4];
                af[0] = tf32_trunc(As[(r0    ) * ASTRIDE + kb + tg    ]);
                af[1] = tf32_trunc(As[(r0 + 8) * ASTRIDE + kb + tg    ]);
                af[2] = tf32_trunc(As[(r0    ) * ASTRIDE + kb + tg + 4]);
                af[3] = tf32_trunc(As[(r0 + 8) * ASTRIDE + kb + tg + 4]);
                #pragma unroll
                for (int ni = 0; ni < 4; ni++)
                    mma_tf32(acc[mi][ni], af, bf[ni]);
            }
        }

        if (kt + 2 < 128) stage(kt + 2);
        else              cp_commit();
    }

    #pragma unroll
    for (int mi = 0; mi < 4; mi++) {
        int r0 = rowTile + wr * 64 + mi * 16 + g;
        int r1 = r0 + 8;
        float cf0 = alpha * cfB[r0];
        float cf1 = alpha * cfB[r1];
        #pragma unroll
        for (int ni = 0; ni < 4; ni++) {
            int c0 = wc * 32 + ni * 8 + tg * 2;
            float2 z0 = *(const float2*)&zB[(size_t)r0 * C_SZ + c0];
            float2 z1 = *(const float2*)&zB[(size_t)r1 * C_SZ + c0];
            float2 x0 = *(const float2*)&xB[(size_t)r0 * C_SZ + c0];
            float2 x1 = *(const float2*)&xB[(size_t)r1 * C_SZ + c0];
            float2 o0, o1;
            o0.x = cf0 * z0.x + beta * acc[mi][ni][0] - x0.x;
            o0.y = cf0 * z0.y + beta * acc[mi][ni][1] - x0.y;
            o1.x = cf1 * z1.x + beta * acc[mi][ni][2] - x1.x;
            o1.y = cf1 * z1.y + beta * acc[mi][ni][3] - x1.y;
            *(float2*)&oB[(size_t)r0 * C_SZ + c0] = o0;
            *(float2*)&oB[(size_t)r1 * C_SZ + c0] = o1;
        }
    }
}

// ---------------------------------------------------------------------------
// Final linear via 3xTF32 (hi/lo mantissa split). W transpose folded into
// the B-staging (register transpose; W is L2-resident).
//   out[r][o] = sum_f Zflat[r][f] * W[o][f]
// ---------------------------------------------------------------------------
__global__ void __launch_bounds__(256, 1)
out_gemm_kernel(const float* __restrict__ W, float* __restrict__ out) {
    extern __shared__ float sm[];
    int rowTile = blockIdx.x * 128;

    int tid  = threadIdx.x;
    int lane = tid & 31;
    int warp = tid >> 5;
    int wr = warp >> 2, wc = warp & 3;
    int g  = lane >> 2, tg = lane & 3;

    float acc[4][4][4];
    #pragma unroll
    for (int i = 0; i < 4; i++)
        #pragma unroll
        for (int j = 0; j < 4; j++)
            #pragma unroll
            for (int v = 0; v < 4; v++) acc[i][j][v] = 0.f;

    auto stage = [&](int t) {
        float* As = sm + (t % STG) * STAGE_FLOATS;
        float* Bs = As + 128 * ASTRIDE;
        int k0 = t * 32;
        #pragma unroll
        for (int it = 0; it < 4; it++) {
            int r = (tid >> 3) + it * 32;
            int q = (tid & 7) * 4;
            cp16(As + r * ASTRIDE + q, g_Z + (size_t)(rowTile + r) * KC + k0 + q);
        }
        cp_commit();
        // B: W[o][k] -> Bs[k][o], register transpose (16 values per thread)
        int o  = tid >> 1;
        int kq = (tid & 1) * 16;
        #pragma unroll
        for (int j = 0; j < 4; j++) {
            float4 v = *(const float4*)(W + (size_t)o * KC + k0 + kq + j * 4);
            Bs[(kq + j * 4 + 0) * BSTRIDE + o] = v.x;
            Bs[(kq + j * 4 + 1) * BSTRIDE + o] = v.y;
            Bs[(kq + j * 4 + 2) * BSTRIDE + o] = v.z;
            Bs[(kq + j * 4 + 3) * BSTRIDE + o] = v.w;
        }
    };

    stage(0); stage(1);

    for (int kt = 0; kt < 12; kt++) {
        cp_wait<1>();
        __syncthreads();

        const float* As = sm + (kt % STG) * STAGE_FLOATS;
        const float* Bs = As + 128 * ASTRIDE;

        #pragma unroll
        for (int ks = 0; ks < 4; ks++) {
            int kb = ks * 8;
            uint32_t bh[4][2], bl[4][2];
            #pragma unroll
            for (int ni = 0; ni < 4; ni++) {
                int col = wc * 32 + ni * 8 + g;
                float v0 = Bs[(kb + tg) * BSTRIDE + col];
                float v1 = Bs[(kb + tg + 4) * BSTRIDE + col];
                bh[ni][0] = tf32_trunc(v0);
                bh[ni][1] = tf32_trunc(v1);
                bl[ni][0] = tf32_trunc(v0 - __uint_as_float(bh[ni][0]));
                bl[ni][1] = tf32_trunc(v1 - __uint_as_float(bh[ni][1]));
            }
            #pragma unroll
            for (int mi = 0; mi < 4; mi++) {
                int r0 = wr * 64 + mi * 16 + g;
                float a0 = As[(r0    ) * ASTRIDE + kb + tg    ];
                float a1 = As[(r0 + 8) * ASTRIDE + kb + tg    ];
                float a2 = As[(r0    ) * ASTRIDE + kb + tg + 4];
                float a3 = As[(r0 + 8) * ASTRIDE + kb + tg + 4];
                uint32_t ah[4], al[4];
                ah[0] = tf32_trunc(a0); ah[1] = tf32_trunc(a1);
                ah[2] = tf32_trunc(a2); ah[3] = tf32_trunc(a3);
                al[0] = tf32_trunc(a0 - __uint_as_float(ah[0]));
                al[1] = tf32_trunc(a1 - __uint_as_float(ah[1]));
                al[2] = tf32_trunc(a2 - __uint_as_float(ah[2]));
                al[3] = tf32_trunc(a3 - __uint_as_float(ah[3]));
                #pragma unroll
                for (int ni = 0; ni < 4; ni++) {
                    mma_tf32(acc[mi][ni], ah, bh[ni]);   // hi*hi
                    mma_tf32(acc[mi][ni], ah, bl[ni]);   // hi*lo
                    mma_tf32(acc[mi][ni], al, bh[ni]);   // lo*hi
                }
            }
        }

        if (kt + 2 < 12) stage(kt + 2);
        else             cp_commit();
    }

    #pragma unroll
    for (int mi = 0; mi < 4; mi++) {
        size_t r0 = (size_t)rowTile + wr * 64 + mi * 16 + g;
        size_t r1 = r0 + 8;
        #pragma unroll
        for (int ni = 0; ni < 4; ni++) {
            int c0 = wc * 32 + ni * 8 + tg * 2;
            *(float2*)&out[r0 * C_SZ + c0] = make_float2(acc[mi][ni][0], acc[mi][ni][1]);
            *(float2*)&out[r1 * C_SZ + c0] = make_float2(acc[mi][ni][2], acc[mi][ni][3]);
        }
    }
}

// ---------------------------------------------------------------------------
extern "C" void kernel_launch(void* const* d_in, const int* in_sizes, int n_in,
                              void* d_out, int out_size) {
    const float* x   = nullptr;
    const float* adj = nullptr;
    const float* W   = nullptr;
    for (int i = 0; i < n_in; i++) {
        long long sz = in_sizes[i];
        if (sz == (long long)B_SZ * N_SZ * N_SZ)      adj = (const float*)d_in[i];
        else if (sz == (long long)B_SZ * N_SZ * C_SZ) x   = (const float*)d_in[i];
        else                                          W   = (const float*)d_in[i];
    }
    float* out = (float*)d_out;

    cudaFuncSetAttribute(cheb1_mma_kernel,
                         cudaFuncAttributeMaxDynamicSharedMemorySize, SMEM_BYTES);
    cudaFuncSetAttribute(cheb2_mma_kernel,
                         cudaFuncAttributeMaxDynamicSharedMemorySize, SMEM_BYTES);
    cudaFuncSetAttribute(out_gemm_kernel,
                         cudaFuncAttributeMaxDynamicSharedMemorySize, SMEM_BYTES);

    cheb1_mma_kernel<<<dim3(N_SZ / 128, B_SZ), 256, SMEM_BYTES>>>(adj, x);
    deg_reduce_kernel<<<(B_SZ * N_SZ) / 256, 256>>>();
    combine1_kernel<<<(unsigned)((B_SZ * NC / 4) / 256), 256>>>(x);
    cheb2_mma_kernel<<<dim3(N_SZ / 128, B_SZ), 256, SMEM_BYTES>>>(adj, x);
    out_gemm_kernel<<<(B_SZ * N_SZ) / 128, 256, SMEM_BYTES>>>(W, out);
}

// round 11
// speedup vs baseline: 3.7657x; 1.0845x over previous
#include <cuda_runtime.h>
#include <cstdint>
#include <cstddef>

#define B_SZ 4
#define N_SZ 4096
#define C_SZ 128
#define KCH  3
#define KC   (KCH * C_SZ)                       // 384
#define NC   ((size_t)N_SZ * C_SZ)              // 524288
#define ZBATCH ((size_t)KCH * N_SZ * C_SZ)      // 1572864

static constexpr float LR = 2.0f / (2.0f + 1e-6f);

// Scratch (device globals: no runtime allocation allowed)
__device__ float g_Z[(size_t)B_SZ * KCH * N_SZ * C_SZ];   // [B][K][N][C]  (24 MB)
__device__ float g_part2[(size_t)B_SZ * 32 * 8 * N_SZ];   // per-(CTA,warp) colsum partials
__device__ float g_coef[B_SZ * N_SZ];                     // lr*deg - 1

// ---------------------------------------------------------------------------
// helpers
// ---------------------------------------------------------------------------
__device__ __forceinline__ unsigned smem_u32(const void* p) {
    return (unsigned)__cvta_generic_to_shared(p);
}
__device__ __forceinline__ void cp16(float* dst, const float* src) {
    asm volatile("cp.async.cg.shared.global [%0], [%1], 16;\n"
                 :: "r"(smem_u32(dst)), "l"(src));
}
__device__ __forceinline__ void cp_commit() { asm volatile("cp.async.commit_group;\n"); }
template <int Nn>
__device__ __forceinline__ void cp_wait() {
    asm volatile("cp.async.wait_group %0;\n" :: "n"(Nn));
}
// tf32 operand by mantissa truncation (RZ) — 1 LOP per value
__device__ __forceinline__ uint32_t tf32_trunc(float x) {
    return __float_as_uint(x) & 0xFFFFE000u;
}
__device__ __forceinline__ void mma_tf32(float* d, const uint32_t* a, const uint32_t* b) {
    asm volatile(
        "mma.sync.aligned.m16n8k8.row.col.f32.tf32.tf32.f32 "
        "{%0,%1,%2,%3}, {%4,%5,%6,%7}, {%8,%9}, {%0,%1,%2,%3};\n"
        : "+f"(d[0]), "+f"(d[1]), "+f"(d[2]), "+f"(d[3])
        : "r"(a[0]), "r"(a[1]), "r"(a[2]), "r"(a[3]), "r"(b[0]), "r"(b[1]));
}

// A tile: 128 rows x 32 floats, XOR-swizzled at 16B-chunk granularity:
//   phys float index = r*32 + ((chunk ^ (r&7))<<2) + (within-chunk)
// -> A-fragment LDS (lanes vary r by g) hit 8 distinct banks: conflict-free.
#define ASTRIDE 32
#define BSTRIDE 136
#define STAGE_FLOATS (128 * ASTRIDE + 32 * BSTRIDE)   // 8448
#define STG 3
#define SMEM_BYTES   (STG * STAGE_FLOATS * 4)         // 101376

__device__ __forceinline__ int aswz(int r, int colf) {
    // colf in [0,32): float column within the A row
    return r * ASTRIDE + ((((colf >> 2) ^ (r & 7)) << 2) | (colf & 3));
}

// ---------------------------------------------------------------------------
// Chebyshev STEP 1 GEMM + fused degree partial column sums.
//   Writes  g_Z slice1 = -LR * (adj @ x)     (combine1 finishes Z1)
//   Writes  g_part2 partial column sums of adj (per CTA,warp).
// ---------------------------------------------------------------------------
__global__ void __launch_bounds__(256, 1)
cheb1_mma_kernel(const float* __restrict__ adj, const float* __restrict__ x) {
    extern __shared__ float sm[];

    int b       = blockIdx.y;
    int rowTile = blockIdx.x * 128;

    const float* adjB = adj + (size_t)b * N_SZ * N_SZ;
    const float* zB   = x + (size_t)b * NC;
    float*       oB   = g_Z + (size_t)b * ZBATCH + NC;      // slice 1
    float*       prt  = g_part2 + (((size_t)b * 32 + blockIdx.x) * 8) * N_SZ;

    int tid  = threadIdx.x;
    int lane = tid & 31;
    int warp = tid >> 5;
    int wr = warp >> 2, wc = warp & 3;
    int g  = lane >> 2, tg = lane & 3;

    float acc[4][4][4];
    #pragma unroll
    for (int i = 0; i < 4; i++)
        #pragma unroll
        for (int j = 0; j < 4; j++)
            #pragma unroll
            for (int v = 0; v < 4; v++) acc[i][j][v] = 0.f;

    auto stage = [&](int t) {
        float* As = sm + (t % STG) * STAGE_FLOATS;
        float* Bs = As + 128 * ASTRIDE;
        int k0 = t * 32;
        #pragma unroll
        for (int it = 0; it < 4; it++) {
            int r = (tid >> 3) + it * 32;
            int q = tid & 7;                               // 16B chunk
            cp16(As + r * ASTRIDE + ((q ^ (r & 7)) << 2),
                 adjB + (size_t)(rowTile + r) * N_SZ + k0 + q * 4);
        }
        #pragma unroll
        for (int it = 0; it < 4; it++) {
            int kr = (tid >> 5) + it * 8;
            int q  = (tid & 31) * 4;
            cp16(Bs + kr * BSTRIDE + q, zB + (size_t)(k0 + kr) * C_SZ + q);
        }
        cp_commit();
    };

    stage(0); stage(1);

    for (int kt = 0; kt < 128; kt++) {
        cp_wait<1>();
        __syncthreads();

        const float* As = sm + (kt % STG) * STAGE_FLOATS;
        const float* Bs = As + 128 * ASTRIDE;

        #pragma unroll
        for (int ks = 0; ks < 4; ks++) {
            int kb = ks * 8;
            // swizzled A offsets: chunk c0=2ks (cols kb+tg), c1=2ks+1 (cols kb+tg+4)
            int offA0 = ((((2 * ks)     ^ g) << 2) | tg);
            int offA1 = ((((2 * ks + 1) ^ g) << 2) | tg);
            uint32_t bf[4][2];
            #pragma unroll
            for (int ni = 0; ni < 4; ni++) {
                int col = wc * 32 + ni * 8 + g;
                bf[ni][0] = tf32_trunc(Bs[(kb + tg) * BSTRIDE + col]);
                bf[ni][1] = tf32_trunc(Bs[(kb + tg + 4) * BSTRIDE + col]);
            }
            #pragma unroll
            for (int mi = 0; mi < 4; mi++) {
                int r0 = wr * 64 + mi * 16 + g;
                uint32_t af[4];
                af[0] = tf32_trunc(As[(r0    ) * ASTRIDE + offA0]);
                af[1] = tf32_trunc(As[(r0 + 8) * ASTRIDE + offA0]);
                af[2] = tf32_trunc(As[(r0    ) * ASTRIDE + offA1]);
                af[3] = tf32_trunc(As[(r0 + 8) * ASTRIDE + offA1]);
                #pragma unroll
                for (int ni = 0; ni < 4; ni++)
                    mma_tf32(acc[mi][ni], af, bf[ni]);
            }
        }

        // fused degree partials: warp sums its 16 rows of col=lane
        {
            float cs = 0.f;
            #pragma unroll
            for (int r = 0; r < 16; r++) {
                int rr = warp * 16 + r;
                cs += As[aswz(rr, lane)];
            }
            prt[(size_t)warp * N_SZ + kt * 32 + lane] = cs;
        }

        if (kt + 2 < 128) stage(kt + 2);
        else              cp_commit();
    }

    // epilogue: store -LR * S (combine1 adds coef*x)
    #pragma unroll
    for (int mi = 0; mi < 4; mi++) {
        int r0 = rowTile + wr * 64 + mi * 16 + g;
        int r1 = r0 + 8;
        #pragma unroll
        for (int ni = 0; ni < 4; ni++) {
            int c0 = wc * 32 + ni * 8 + tg * 2;
            *(float2*)&oB[(size_t)r0 * C_SZ + c0] =
                make_float2(-LR * acc[mi][ni][0], -LR * acc[mi][ni][1]);
            *(float2*)&oB[(size_t)r1 * C_SZ + c0] =
                make_float2(-LR * acc[mi][ni][2], -LR * acc[mi][ni][3]);
        }
    }
}

// ---------------------------------------------------------------------------
// coef[b][m] = LR * (sum of 256 partials) - 1
// ---------------------------------------------------------------------------
__global__ void deg_reduce_kernel() {
    int i = blockIdx.x * blockDim.x + threadIdx.x;   // 0..16383 = b*4096 + m
    int b = i >> 12, m = i & 4095;
    float s = 0.f;
    #pragma unroll 8
    for (int j = 0; j < 256; j++)
        s += g_part2[((size_t)b * 256 + j) * N_SZ + m];
    g_coef[i] = LR * s - 1.0f;
}

// ---------------------------------------------------------------------------
// combine1: slice0 = x;  slice1 = coef*x + slice1   (slice1 held -LR*S)
// ---------------------------------------------------------------------------
__global__ void combine1_kernel(const float* __restrict__ x) {
    size_t i   = (size_t)blockIdx.x * blockDim.x + threadIdx.x;  // float4 index
    size_t b   = i / (NC / 4);
    size_t rem = i % (NC / 4);
    size_t row = rem >> 5;                                       // C/4 = 32
    float cf = g_coef[b * N_SZ + row];
    float4 xv = ((const float4*)x)[i];
    float4* z0 = (float4*)g_Z + b * (ZBATCH / 4) + rem;
    float4* z1 = z0 + NC / 4;
    float4 s1 = *z1;
    s1.x += cf * xv.x; s1.y += cf * xv.y; s1.z += cf * xv.z; s1.w += cf * xv.w;
    *z0 = xv;
    *z1 = s1;
}

// ---------------------------------------------------------------------------
// Chebyshev STEP 2 GEMM with fused epilogue:
//   out = 2*coef*z - 2*lr*(adj@z) - x,   z = Z1
// ---------------------------------------------------------------------------
__global__ void __launch_bounds__(256, 1)
cheb2_mma_kernel(const float* __restrict__ adj, const float* __restrict__ x) {
    extern __shared__ float sm[];
    constexpr float alpha = 2.0f;
    constexpr float beta  = -2.0f * LR;

    int b       = blockIdx.y;
    int rowTile = blockIdx.x * 128;

    const float* adjB = adj + (size_t)b * N_SZ * N_SZ;
    const float* zB   = g_Z + (size_t)b * ZBATCH + NC;       // slice 1
    float*       oB   = g_Z + (size_t)b * ZBATCH + 2 * NC;   // slice 2
    const float* xB   = x + (size_t)b * NC;
    const float* cfB  = g_coef + b * N_SZ;

    int tid  = threadIdx.x;
    int lane = tid & 31;
    int warp = tid >> 5;
    int wr = warp >> 2, wc = warp & 3;
    int g  = lane >> 2, tg = lane & 3;

    float acc[4][4][4];
    #pragma unroll
    for (int i = 0; i < 4; i++)
        #pragma unroll
        for (int j = 0; j < 4; j++)
            #pragma unroll
            for (int v = 0; v < 4; v++) acc[i][j][v] = 0.f;

    auto stage = [&](int t) {
        float* As = sm + (t % STG) * STAGE_FLOATS;
        float* Bs = As + 128 * ASTRIDE;
        int k0 = t * 32;
        #pragma unroll
        for (int it = 0; it < 4; it++) {
            int r = (tid >> 3) + it * 32;
            int q = tid & 7;
            cp16(As + r * ASTRIDE + ((q ^ (r & 7)) << 2),
                 adjB + (size_t)(rowTile + r) * N_SZ + k0 + q * 4);
        }
        #pragma unroll
        for (int it = 0; it < 4; it++) {
            int kr = (tid >> 5) + it * 8;
            int q  = (tid & 31) * 4;
            cp16(Bs + kr * BSTRIDE + q, zB + (size_t)(k0 + kr) * C_SZ + q);
        }
        cp_commit();
    };

    stage(0); stage(1);

    for (int kt = 0; kt < 128; kt++) {
        cp_wait<1>();
        __syncthreads();

        const float* As = sm + (kt % STG) * STAGE_FLOATS;
        const float* Bs = As + 128 * ASTRIDE;

        #pragma unroll
        for (int ks = 0; ks < 4; ks++) {
            int kb = ks * 8;
            int offA0 = ((((2 * ks)     ^ g) << 2) | tg);
            int offA1 = ((((2 * ks + 1) ^ g) << 2) | tg);
            uint32_t bf[4][2];
            #pragma unroll
            for (int ni = 0; ni < 4; ni++) {
                int col = wc * 32 + ni * 8 + g;
                bf[ni][0] = tf32_trunc(Bs[(kb + tg) * BSTRIDE + col]);
                bf[ni][1] = tf32_trunc(Bs[(kb + tg + 4) * BSTRIDE + col]);
            }
            #pragma unroll
            for (int mi = 0; mi < 4; mi++) {
                int r0 = wr * 64 + mi * 16 + g;
                uint32_t af[4];
                af[0] = tf32_trunc(As[(r0    ) * ASTRIDE + offA0]);
                af[1] = tf32_trunc(As[(r0 + 8) * ASTRIDE + offA0]);
                af[2] = tf32_trunc(As[(r0    ) * ASTRIDE + offA1]);
                af[3] = tf32_trunc(As[(r0 + 8) * ASTRIDE + offA1]);
                #pragma unroll
                for (int ni = 0; ni < 4; ni++)
                    mma_tf32(acc[mi][ni], af, bf[ni]);
            }
        }

        if (kt + 2 < 128) stage(kt + 2);
        else              cp_commit();
    }

    #pragma unroll
    for (int mi = 0; mi < 4; mi++) {
        int r0 = rowTile + wr * 64 + mi * 16 + g;
        int r1 = r0 + 8;
        float cf0 = alpha * cfB[r0];
        float cf1 = alpha * cfB[r1];
        #pragma unroll
        for (int ni = 0; ni < 4; ni++) {
            int c0 = wc * 32 + ni * 8 + tg * 2;
            float2 z0 = *(const float2*)&zB[(size_t)r0 * C_SZ + c0];
            float2 z1 = *(const float2*)&zB[(size_t)r1 * C_SZ + c0];
            float2 x0 = *(const float2*)&xB[(size_t)r0 * C_SZ + c0];
            float2 x1 = *(const float2*)&xB[(size_t)r1 * C_SZ + c0];
            float2 o0, o1;
            o0.x = cf0 * z0.x + beta * acc[mi][ni][0] - x0.x;
            o0.y = cf0 * z0.y + beta * acc[mi][ni][1] - x0.y;
            o1.x = cf1 * z1.x + beta * acc[mi][ni][2] - x1.x;
            o1.y = cf1 * z1.y + beta * acc[mi][ni][3] - x1.y;
            *(float2*)&oB[(size_t)r0 * C_SZ + c0] = o0;
            *(float2*)&oB[(size_t)r1 * C_SZ + c0] = o1;
        }
    }
}

// ---------------------------------------------------------------------------
// Final linear via 3xTF32 (hi/lo mantissa split). W transpose folded into
// the B-staging (register transpose; W is L2-resident).
//   out[r][o] = sum_f Zflat[r][f] * W[o][f]
// ---------------------------------------------------------------------------
__global__ void __launch_bounds__(256, 1)
out_gemm_kernel(const float* __restrict__ W, float* __restrict__ out) {
    extern __shared__ float sm[];
    int rowTile = blockIdx.x * 128;

    int tid  = threadIdx.x;
    int lane = tid & 31;
    int warp = tid >> 5;
    int wr = warp >> 2, wc = warp & 3;
    int g  = lane >> 2, tg = lane & 3;

    float acc[4][4][4];
    #pragma unroll
    for (int i = 0; i < 4; i++)
        #pragma unroll
        for (int j = 0; j < 4; j++)
            #pragma unroll
            for (int v = 0; v < 4; v++) acc[i][j][v] = 0.f;

    auto stage = [&](int t) {
        float* As = sm + (t % STG) * STAGE_FLOATS;
        float* Bs = As + 128 * ASTRIDE;
        int k0 = t * 32;
        #pragma unroll
        for (int it = 0; it < 4; it++) {
            int r = (tid >> 3) + it * 32;
            int q = tid & 7;
            cp16(As + r * ASTRIDE + ((q ^ (r & 7)) << 2),
                 g_Z + (size_t)(rowTile + r) * KC + k0 + q * 4);
        }
        cp_commit();
        // B: W[o][k] -> Bs[k][o], register transpose
        int o  = tid >> 1;
        int kq = (tid & 1) * 16;
        #pragma unroll
        for (int j = 0; j < 4; j++) {
            float4 v = *(const float4*)(W + (size_t)o * KC + k0 + kq + j * 4);
            Bs[(kq + j * 4 + 0) * BSTRIDE + o] = v.x;
            Bs[(kq + j * 4 + 1) * BSTRIDE + o] = v.y;
            Bs[(kq + j * 4 + 2) * BSTRIDE + o] = v.z;
            Bs[(kq + j * 4 + 3) * BSTRIDE + o] = v.w;
        }
    };

    stage(0); stage(1);

    for (int kt = 0; kt < 12; kt++) {
        cp_wait<1>();
        __syncthreads();

        const float* As = sm + (kt % STG) * STAGE_FLOATS;
        const float* Bs = As + 128 * ASTRIDE;

        #pragma unroll
        for (int ks = 0; ks < 4; ks++) {
            int kb = ks * 8;
            int offA0 = ((((2 * ks)     ^ g) << 2) | tg);
            int offA1 = ((((2 * ks + 1) ^ g) << 2) | tg);
            uint32_t bh[4][2], bl[4][2];
            #pragma unroll
            for (int ni = 0; ni < 4; ni++) {
                int col = wc * 32 + ni * 8 + g;
                float v0 = Bs[(kb + tg) * BSTRIDE + col];
                float v1 = Bs[(kb + tg + 4) * BSTRIDE + col];
                bh[ni][0] = tf32_trunc(v0);
                bh[ni][1] = tf32_trunc(v1);
                bl[ni][0] = tf32_trunc(v0 - __uint_as_float(bh[ni][0]));
                bl[ni][1] = tf32_trunc(v1 - __uint_as_float(bh[ni][1]));
            }
            #pragma unroll
            for (int mi = 0; mi < 4; mi++) {
                int r0 = wr * 64 + mi * 16 + g;
                float a0 = As[(r0    ) * ASTRIDE + offA0];
                float a1 = As[(r0 + 8) * ASTRIDE + offA0];
                float a2 = As[(r0    ) * ASTRIDE + offA1];
                float a3 = As[(r0 + 8) * ASTRIDE + offA1];
                uint32_t ah[4], al[4];
                ah[0] = tf32_trunc(a0); ah[1] = tf32_trunc(a1);
                ah[2] = tf32_trunc(a2); ah[3] = tf32_trunc(a3);
                al[0] = tf32_trunc(a0 - __uint_as_float(ah[0]));
                al[1] = tf32_trunc(a1 - __uint_as_float(ah[1]));
                al[2] = tf32_trunc(a2 - __uint_as_float(ah[2]));
                al[3] = tf32_trunc(a3 - __uint_as_float(ah[3]));
                #pragma unroll
                for (int ni = 0; ni < 4; ni++) {
                    mma_tf32(acc[mi][ni], ah, bh[ni]);   // hi*hi
                    mma_tf32(acc[mi][ni], ah, bl[ni]);   // hi*lo
                    mma_tf32(acc[mi][ni], al, bh[ni]);   // lo*hi
                }
            }
        }

        if (kt + 2 < 12) stage(kt + 2);
        else             cp_commit();
    }

    #pragma unroll
    for (int mi = 0; mi < 4; mi++) {
        size_t r0 = (size_t)rowTile + wr * 64 + mi * 16 + g;
        size_t r1 = r0 + 8;
        #pragma unroll
        for (int ni = 0; ni < 4; ni++) {
            int c0 = wc * 32 + ni * 8 + tg * 2;
            *(float2*)&out[r0 * C_SZ + c0] = make_float2(acc[mi][ni][0], acc[mi][ni][1]);
            *(float2*)&out[r1 * C_SZ + c0] = make_float2(acc[mi][ni][2], acc[mi][ni][3]);
        }
    }
}

// ---------------------------------------------------------------------------
extern "C" void kernel_launch(void* const* d_in, const int* in_sizes, int n_in,
                              void* d_out, int out_size) {
    const float* x   = nullptr;
    const float* adj = nullptr;
    const float* W   = nullptr;
    for (int i = 0; i < n_in; i++) {
        long long sz = in_sizes[i];
        if (sz == (long long)B_SZ * N_SZ * N_SZ)      adj = (const float*)d_in[i];
        else if (sz == (long long)B_SZ * N_SZ * C_SZ) x   = (const float*)d_in[i];
        else                                          W   = (const float*)d_in[i];
    }
    float* out = (float*)d_out;

    cudaFuncSetAttribute(cheb1_mma_kernel,
                         cudaFuncAttributeMaxDynamicSharedMemorySize, SMEM_BYTES);
    cudaFuncSetAttribute(cheb2_mma_kernel,
                         cudaFuncAttributeMaxDynamicSharedMemorySize, SMEM_BYTES);
    cudaFuncSetAttribute(out_gemm_kernel,
                         cudaFuncAttributeMaxDynamicSharedMemorySize, SMEM_BYTES);

    cheb1_mma_kernel<<<dim3(N_SZ / 128, B_SZ), 256, SMEM_BYTES>>>(adj, x);
    deg_reduce_kernel<<<(B_SZ * N_SZ) / 256, 256>>>();
    combine1_kernel<<<(unsigned)((B_SZ * NC / 4) / 256), 256>>>(x);
    cheb2_mma_kernel<<<dim3(N_SZ / 128, B_SZ), 256, SMEM_BYTES>>>(adj, x);
    out_gemm_kernel<<<(B_SZ * N_SZ) / 128, 256, SMEM_BYTES>>>(W, out);
}

// round 14
// speedup vs baseline: 3.8513x; 1.0228x over previous
#include <cuda_runtime.h>
#include <cstdint>
#include <cstddef>

#define B_SZ 4
#define N_SZ 4096
#define C_SZ 128
#define KCH  3
#define KC   (KCH * C_SZ)                       // 384
#define NC   ((size_t)N_SZ * C_SZ)              // 524288
#define ZBATCH ((size_t)KCH * N_SZ * C_SZ)      // 1572864

static constexpr float LR = 2.0f / (2.0f + 1e-6f);

// Scratch (device globals: no runtime allocation allowed)
__device__ float g_Z[(size_t)B_SZ * KCH * N_SZ * C_SZ];   // [B][K][N][C]  (24 MB)
__device__ float g_Sp1[(size_t)B_SZ * N_SZ * C_SZ];       // split-K h=1 partial (8 MB)
__device__ float g_part2[(size_t)B_SZ * 32 * 8 * N_SZ];   // colsum partials
__device__ float g_coef[B_SZ * N_SZ];                     // lr*deg - 1

// ---------------------------------------------------------------------------
// helpers
// ---------------------------------------------------------------------------
__device__ __forceinline__ unsigned smem_u32(const void* p) {
    return (unsigned)__cvta_generic_to_shared(p);
}
__device__ __forceinline__ void cp16(float* dst, const float* src) {
    asm volatile("cp.async.cg.shared.global [%0], [%1], 16;\n"
                 :: "r"(smem_u32(dst)), "l"(src));
}
__device__ __forceinline__ void cp_commit() { asm volatile("cp.async.commit_group;\n"); }
template <int Nn>
__device__ __forceinline__ void cp_wait() {
    asm volatile("cp.async.wait_group %0;\n" :: "n"(Nn));
}
__device__ __forceinline__ uint32_t tf32_trunc(float x) {
    return __float_as_uint(x) & 0xFFFFE000u;
}
__device__ __forceinline__ void mma_tf32(float* d, const uint32_t* a, const uint32_t* b) {
    asm volatile(
        "mma.sync.aligned.m16n8k8.row.col.f32.tf32.tf32.f32 "
        "{%0,%1,%2,%3}, {%4,%5,%6,%7}, {%8,%9}, {%0,%1,%2,%3};\n"
        : "+f"(d[0]), "+f"(d[1]), "+f"(d[2]), "+f"(d[3])
        : "r"(a[0]), "r"(a[1]), "r"(a[2]), "r"(a[3]), "r"(b[0]), "r"(b[1]));
}

#define ASTRIDE 32
#define BSTRIDE 136
#define STAGE_FLOATS (128 * ASTRIDE + 32 * BSTRIDE)   // 8448
#define STG 3
#define SMEM_BYTES   (STG * STAGE_FLOATS * 4)         // 101376

__device__ __forceinline__ int aswz(int r, int colf) {
    return r * ASTRIDE + ((((colf >> 2) ^ (r & 7)) << 2) | (colf & 3));
}

// ---------------------------------------------------------------------------
// Split-K Chebyshev GEMM: raw partial S_h[n][c] = sum_{m in half h}
// adj[n][m] * z[m][c]; stores UNSCALED partial (combine kernels finish).
// Batch strides passed explicitly (g_Z slices stride ZBATCH; x/Sp1 stride NC).
// DO_COLSUM: also writes adj column-sum partials (cheb1 only).
// grid (32 rowtiles, B, 2 halves); 2 CTAs/SM via launch_bounds(256,2).
// ---------------------------------------------------------------------------
template <int DO_COLSUM>
__global__ void __launch_bounds__(256, 2)
cheb_split_kernel(const float* __restrict__ adj,
                  const float* __restrict__ z,  size_t zStride,
                  float* __restrict__ out0,     size_t o0Stride,
                  float* __restrict__ out1,     size_t o1Stride) {
    extern __shared__ float sm[];

    int b       = blockIdx.y;
    int h       = blockIdx.z;
    int rowTile = blockIdx.x * 128;

    const float* adjB = adj + (size_t)b * N_SZ * N_SZ;
    const float* zB   = z + (size_t)b * zStride;
    float*       oB   = (h == 0) ? (out0 + (size_t)b * o0Stride)
                                 : (out1 + (size_t)b * o1Stride);
    float*       prt  = g_part2 + (((size_t)b * 32 + blockIdx.x) * 8) * N_SZ;

    int tid  = threadIdx.x;
    int lane = tid & 31;
    int warp = tid >> 5;
    int wr = warp >> 2, wc = warp & 3;
    int g  = lane >> 2, tg = lane & 3;

    int ktBase = h * 64;                       // 64 k-iters per half

    float acc[4][4][4];
    #pragma unroll
    for (int i = 0; i < 4; i++)
        #pragma unroll
        for (int j = 0; j < 4; j++)
            #pragma unroll
            for (int v = 0; v < 4; v++) acc[i][j][v] = 0.f;

    auto stage = [&](int t) {
        float* As = sm + (t % STG) * STAGE_FLOATS;
        float* Bs = As + 128 * ASTRIDE;
        int k0 = (ktBase + t) * 32;
        #pragma unroll
        for (int it = 0; it < 4; it++) {
            int r = (tid >> 3) + it * 32;
            int q = tid & 7;
            cp16(As + r * ASTRIDE + ((q ^ (r & 7)) << 2),
                 adjB + (size_t)(rowTile + r) * N_SZ + k0 + q * 4);
        }
        #pragma unroll
        for (int it = 0; it < 4; it++) {
            int kr = (tid >> 5) + it * 8;
            int q  = (tid & 31) * 4;
            cp16(Bs + kr * BSTRIDE + q, zB + (size_t)(k0 + kr) * C_SZ + q);
        }
        cp_commit();
    };

    stage(0); stage(1);

    for (int kt = 0; kt < 64; kt++) {
        cp_wait<1>();
        __syncthreads();

        const float* As = sm + (kt % STG) * STAGE_FLOATS;
        const float* Bs = As + 128 * ASTRIDE;

        #pragma unroll
        for (int ks = 0; ks < 4; ks++) {
            int kb = ks * 8;
            int offA0 = ((((2 * ks)     ^ g) << 2) | tg);
            int offA1 = ((((2 * ks + 1) ^ g) << 2) | tg);
            uint32_t bf[4][2];
            #pragma unroll
            for (int ni = 0; ni < 4; ni++) {
                int col = wc * 32 + ni * 8 + g;
                bf[ni][0] = tf32_trunc(Bs[(kb + tg) * BSTRIDE + col]);
                bf[ni][1] = tf32_trunc(Bs[(kb + tg + 4) * BSTRIDE + col]);
            }
            #pragma unroll
            for (int mi = 0; mi < 4; mi++) {
                int r0 = wr * 64 + mi * 16 + g;
                uint32_t af[4];
                af[0] = tf32_trunc(As[(r0    ) * ASTRIDE + offA0]);
                af[1] = tf32_trunc(As[(r0 + 8) * ASTRIDE + offA0]);
                af[2] = tf32_trunc(As[(r0    ) * ASTRIDE + offA1]);
                af[3] = tf32_trunc(As[(r0 + 8) * ASTRIDE + offA1]);
                #pragma unroll
                for (int ni = 0; ni < 4; ni++)
                    mma_tf32(acc[mi][ni], af, bf[ni]);
            }
        }

        if (DO_COLSUM) {
            // adj column partial sums over this CTA's 128 rows (warp: 16 rows)
            float cs = 0.f;
            #pragma unroll
            for (int r = 0; r < 16; r++) {
                int rr = warp * 16 + r;
                cs += As[aswz(rr, lane)];
            }
            prt[(size_t)warp * N_SZ + (ktBase + kt) * 32 + lane] = cs;
        }

        if (kt + 2 < 64) stage(kt + 2);
        else             cp_commit();
    }

    // store raw partial S_h
    #pragma unroll
    for (int mi = 0; mi < 4; mi++) {
        int r0 = rowTile + wr * 64 + mi * 16 + g;
        int r1 = r0 + 8;
        #pragma unroll
        for (int ni = 0; ni < 4; ni++) {
            int c0 = wc * 32 + ni * 8 + tg * 2;
            *(float2*)&oB[(size_t)r0 * C_SZ + c0] = make_float2(acc[mi][ni][0], acc[mi][ni][1]);
            *(float2*)&oB[(size_t)r1 * C_SZ + c0] = make_float2(acc[mi][ni][2], acc[mi][ni][3]);
        }
    }
}

// ---------------------------------------------------------------------------
// coef[b][m] = LR * (sum of 256 partials) - 1
// ---------------------------------------------------------------------------
__global__ void deg_reduce_kernel() {
    int i = blockIdx.x * blockDim.x + threadIdx.x;   // b*4096 + m
    int b = i >> 12, m = i & 4095;
    float s = 0.f;
    #pragma unroll 8
    for (int j = 0; j < 256; j++)
        s += g_part2[((size_t)b * 256 + j) * N_SZ + m];
    g_coef[i] = LR * s - 1.0f;
}

// ---------------------------------------------------------------------------
// combine1: slice0 = x;  slice1 = coef*x - LR*(slice1 + Sp1)
// ---------------------------------------------------------------------------
__global__ void combine1_kernel(const float* __restrict__ x) {
    size_t i   = (size_t)blockIdx.x * blockDim.x + threadIdx.x;  // float4 index
    size_t b   = i / (NC / 4);
    size_t rem = i % (NC / 4);
    size_t row = rem >> 5;
    float cf = g_coef[b * N_SZ + row];
    float4 xv = ((const float4*)x)[i];
    float4 s1 = ((const float4*)g_Sp1)[i];
    float4* z0 = (float4*)g_Z + b * (ZBATCH / 4) + rem;
    float4* z1 = z0 + NC / 4;
    float4 s0 = *z1;
    float4 o;
    o.x = cf * xv.x - LR * (s0.x + s1.x);
    o.y = cf * xv.y - LR * (s0.y + s1.y);
    o.z = cf * xv.z - LR * (s0.z + s1.z);
    o.w = cf * xv.w - LR * (s0.w + s1.w);
    *z0 = xv;
    *z1 = o;
}

// ---------------------------------------------------------------------------
// combine2: slice2 = 2*coef*z1 - 2*LR*(slice2 + Sp1) - x
// ---------------------------------------------------------------------------
__global__ void combine2_kernel(const float* __restrict__ x) {
    size_t i   = (size_t)blockIdx.x * blockDim.x + threadIdx.x;
    size_t b   = i / (NC / 4);
    size_t rem = i % (NC / 4);
    size_t row = rem >> 5;
    float cf2 = 2.0f * g_coef[b * N_SZ + row];
    float4 xv = ((const float4*)x)[i];
    float4 s1 = ((const float4*)g_Sp1)[i];
    const float4* z1 = (const float4*)g_Z + b * (ZBATCH / 4) + NC / 4 + rem;
    float4* z2 = (float4*)g_Z + b * (ZBATCH / 4) + 2 * (NC / 4) + rem;
    float4 zv = *z1;
    float4 s0 = *z2;
    float4 o;
    o.x = cf2 * zv.x - 2.0f * LR * (s0.x + s1.x) - xv.x;
    o.y = cf2 * zv.y - 2.0f * LR * (s0.y + s1.y) - xv.y;
    o.z = cf2 * zv.z - 2.0f * LR * (s0.z + s1.z) - xv.z;
    o.w = cf2 * zv.w - 2.0f * LR * (s0.w + s1.w) - xv.w;
    *z2 = o;
}

// ---------------------------------------------------------------------------
// Final linear via 3xTF32 (hi/lo mantissa split). W transpose folded into
// B-staging.  out[r][o] = sum_f Zflat[r][f] * W[o][f]
// ---------------------------------------------------------------------------
__global__ void __launch_bounds__(256, 1)
out_gemm_kernel(const float* __restrict__ W, float* __restrict__ out) {
    extern __shared__ float sm[];
    int rowTile = blockIdx.x * 128;

    int tid  = threadIdx.x;
    int lane = tid & 31;
    int warp = tid >> 5;
    int wr = warp >> 2, wc = warp & 3;
    int g  = lane >> 2, tg = lane & 3;

    float acc[4][4][4];
    #pragma unroll
    for (int i = 0; i < 4; i++)
        #pragma unroll
        for (int j = 0; j < 4; j++)
            #pragma unroll
            for (int v = 0; v < 4; v++) acc[i][j][v] = 0.f;

    auto stage = [&](int t) {
        float* As = sm + (t % STG) * STAGE_FLOATS;
        float* Bs = As + 128 * ASTRIDE;
        int k0 = t * 32;
        #pragma unroll
        for (int it = 0; it < 4; it++) {
            int r = (tid >> 3) + it * 32;
            int q = tid & 7;
            cp16(As + r * ASTRIDE + ((q ^ (r & 7)) << 2),
                 g_Z + (size_t)(rowTile + r) * KC + k0 + q * 4);
        }
        cp_commit();
        int o  = tid >> 1;
        int kq = (tid & 1) * 16;
        #pragma unroll
        for (int j = 0; j < 4; j++) {
            float4 v = *(const float4*)(W + (size_t)o * KC + k0 + kq + j * 4);
            Bs[(kq + j * 4 + 0) * BSTRIDE + o] = v.x;
            Bs[(kq + j * 4 + 1) * BSTRIDE + o] = v.y;
            Bs[(kq + j * 4 + 2) * BSTRIDE + o] = v.z;
            Bs[(kq + j * 4 + 3) * BSTRIDE + o] = v.w;
        }
    };

    stage(0); stage(1);

    for (int kt = 0; kt < 12; kt++) {
        cp_wait<1>();
        __syncthreads();

        const float* As = sm + (kt % STG) * STAGE_FLOATS;
        const float* Bs = As + 128 * ASTRIDE;

        #pragma unroll
        for (int ks = 0; ks < 4; ks++) {
            int kb = ks * 8;
            int offA0 = ((((2 * ks)     ^ g) << 2) | tg);
            int offA1 = ((((2 * ks + 1) ^ g) << 2) | tg);
            uint32_t bh[4][2], bl[4][2];
            #pragma unroll
            for (int ni = 0; ni < 4; ni++) {
                int col = wc * 32 + ni * 8 + g;
                float v0 = Bs[(kb + tg) * BSTRIDE + col];
                float v1 = Bs[(kb + tg + 4) * BSTRIDE + col];
                bh[ni][0] = tf32_trunc(v0);
                bh[ni][1] = tf32_trunc(v1);
                bl[ni][0] = tf32_trunc(v0 - __uint_as_float(bh[ni][0]));
                bl[ni][1] = tf32_trunc(v1 - __uint_as_float(bh[ni][1]));
            }
            #pragma unroll
            for (int mi = 0; mi < 4; mi++) {
                int r0 = wr * 64 + mi * 16 + g;
                float a0 = As[(r0    ) * ASTRIDE + offA0];
                float a1 = As[(r0 + 8) * ASTRIDE + offA0];
                float a2 = As[(r0    ) * ASTRIDE + offA1];
                float a3 = As[(r0 + 8) * ASTRIDE + offA1];
                uint32_t ah[4], al[4];
                ah[0] = tf32_trunc(a0); ah[1] = tf32_trunc(a1);
                ah[2] = tf32_trunc(a2); ah[3] = tf32_trunc(a3);
                al[0] = tf32_trunc(a0 - __uint_as_float(ah[0]));
                al[1] = tf32_trunc(a1 - __uint_as_float(ah[1]));
                al[2] = tf32_trunc(a2 - __uint_as_float(ah[2]));
                al[3] = tf32_trunc(a3 - __uint_as_float(ah[3]));
                #pragma unroll
                for (int ni = 0; ni < 4; ni++) {
                    mma_tf32(acc[mi][ni], ah, bh[ni]);
                    mma_tf32(acc[mi][ni], ah, bl[ni]);
                    mma_tf32(acc[mi][ni], al, bh[ni]);
                }
            }
        }

        if (kt + 2 < 12) stage(kt + 2);
        else             cp_commit();
    }

    #pragma unroll
    for (int mi = 0; mi < 4; mi++) {
        size_t r0 = (size_t)rowTile + wr * 64 + mi * 16 + g;
        size_t r1 = r0 + 8;
        #pragma unroll
        for (int ni = 0; ni < 4; ni++) {
            int c0 = wc * 32 + ni * 8 + tg * 2;
            *(float2*)&out[r0 * C_SZ + c0] = make_float2(acc[mi][ni][0], acc[mi][ni][1]);
            *(float2*)&out[r1 * C_SZ + c0] = make_float2(acc[mi][ni][2], acc[mi][ni][3]);
        }
    }
}

// ---------------------------------------------------------------------------
extern "C" void kernel_launch(void* const* d_in, const int* in_sizes, int n_in,
                              void* d_out, int out_size) {
    const float* x   = nullptr;
    const float* adj = nullptr;
    const float* W   = nullptr;
    for (int i = 0; i < n_in; i++) {
        long long sz = in_sizes[i];
        if (sz == (long long)B_SZ * N_SZ * N_SZ)      adj = (const float*)d_in[i];
        else if (sz == (long long)B_SZ * N_SZ * C_SZ) x   = (const float*)d_in[i];
        else                                          W   = (const float*)d_in[i];
    }
    float* out = (float*)d_out;

    cudaFuncSetAttribute(cheb_split_kernel<1>,
                         cudaFuncAttributeMaxDynamicSharedMemorySize, SMEM_BYTES);
    cudaFuncSetAttribute(cheb_split_kernel<0>,
                         cudaFuncAttributeMaxDynamicSharedMemorySize, SMEM_BYTES);
    cudaFuncSetAttribute(out_gemm_kernel,
                         cudaFuncAttributeMaxDynamicSharedMemorySize, SMEM_BYTES);

    float* g_Z_ptr;    cudaGetSymbolAddress((void**)&g_Z_ptr, g_Z);
    float* g_Sp1_ptr;  cudaGetSymbolAddress((void**)&g_Sp1_ptr, g_Sp1);

    // cheb1: S = adj @ x  (split-K: h=0 -> slice1 [stride ZBATCH],
    //                       h=1 -> Sp1 [stride NC]), fused colsums
    cheb_split_kernel<1><<<dim3(32, B_SZ, 2), 256, SMEM_BYTES>>>(
        adj, x, NC, g_Z_ptr + NC, ZBATCH, g_Sp1_ptr, NC);
    deg_reduce_kernel<<<(B_SZ * N_SZ) / 256, 256>>>();
    combine1_kernel<<<(unsigned)((B_SZ * NC / 4) / 256), 256>>>(x);

    // cheb2: T = adj @ Z1  (z stride ZBATCH; h=0 -> slice2, h=1 -> Sp1)
    cheb_split_kernel<0><<<dim3(32, B_SZ, 2), 256, SMEM_BYTES>>>(
        adj, g_Z_ptr + NC, ZBATCH, g_Z_ptr + 2 * NC, ZBATCH, g_Sp1_ptr, NC);
    combine2_kernel<<<(unsigned)((B_SZ * NC / 4) / 256), 256>>>(x);

    out_gemm_kernel<<<(B_SZ * N_SZ) / 128, 256, SMEM_BYTES>>>(W, out);
}

// round 15
// speedup vs baseline: 4.0393x; 1.0488x over previous
#include <cuda_runtime.h>
#include <cstdint>
#include <cstddef>

#define B_SZ 4
#define N_SZ 4096
#define C_SZ 128
#define KCH  3
#define KC   (KCH * C_SZ)                       // 384
#define NC   ((size_t)N_SZ * C_SZ)              // 524288
#define ZBATCH ((size_t)KCH * N_SZ * C_SZ)      // 1572864
#define NPAIR 2048                              // N_SZ/2 bf16 pairs

static constexpr float LR = 2.0f / (2.0f + 1e-6f);

// Scratch (device globals: no runtime allocation allowed)
__device__ float    g_Z[(size_t)B_SZ * KCH * N_SZ * C_SZ];   // 24 MB
__device__ float    g_Sp1[(size_t)B_SZ * N_SZ * C_SZ];       // split-K h=1 partial (8 MB)
__device__ float    g_part2[(size_t)B_SZ * 32 * 8 * N_SZ];   // colsum partials
__device__ float    g_coef[B_SZ * N_SZ];                     // lr*deg - 1
__device__ uint32_t g_adj16[(size_t)B_SZ * N_SZ * NPAIR];    // adj bf16x2-packed (128 MB)
__device__ uint32_t g_z16[(size_t)B_SZ * NPAIR * C_SZ];      // Z1 bf16, k-pair packed (4 MB)

// ---------------------------------------------------------------------------
// helpers
// ---------------------------------------------------------------------------
__device__ __forceinline__ unsigned smem_u32(const void* p) {
    return (unsigned)__cvta_generic_to_shared(p);
}
__device__ __forceinline__ void cp16(void* dst, const void* src) {
    asm volatile("cp.async.cg.shared.global [%0], [%1], 16;\n"
                 :: "r"(smem_u32(dst)), "l"(src));
}
__device__ __forceinline__ void cp_commit() { asm volatile("cp.async.commit_group;\n"); }
template <int Nn>
__device__ __forceinline__ void cp_wait() {
    asm volatile("cp.async.wait_group %0;\n" :: "n"(Nn));
}
__device__ __forceinline__ uint32_t tf32_trunc(float x) {
    return __float_as_uint(x) & 0xFFFFE000u;
}
// pack two floats into bf16x2 (lo = first k, hi = second k)
__device__ __forceinline__ uint32_t pack_bf16(float lo, float hi) {
    uint32_t d;
    asm("cvt.rn.bf16x2.f32 %0, %1, %2;" : "=r"(d) : "f"(hi), "f"(lo));
    return d;
}
__device__ __forceinline__ void mma_tf32(float* d, const uint32_t* a, const uint32_t* b) {
    asm volatile(
        "mma.sync.aligned.m16n8k8.row.col.f32.tf32.tf32.f32 "
        "{%0,%1,%2,%3}, {%4,%5,%6,%7}, {%8,%9}, {%0,%1,%2,%3};\n"
        : "+f"(d[0]), "+f"(d[1]), "+f"(d[2]), "+f"(d[3])
        : "r"(a[0]), "r"(a[1]), "r"(a[2]), "r"(a[3]), "r"(b[0]), "r"(b[1]));
}
__device__ __forceinline__ void mma_bf16(float* d, const uint32_t* a, const uint32_t* b) {
    asm volatile(
        "mma.sync.aligned.m16n8k16.row.col.f32.bf16.bf16.f32 "
        "{%0,%1,%2,%3}, {%4,%5,%6,%7}, {%8,%9}, {%0,%1,%2,%3};\n"
        : "+f"(d[0]), "+f"(d[1]), "+f"(d[2]), "+f"(d[3])
        : "r"(a[0]), "r"(a[1]), "r"(a[2]), "r"(a[3]), "r"(b[0]), "r"(b[1]));
}

#define ASTRIDE 32
#define BSTRIDE 136
#define STAGE_FLOATS (128 * ASTRIDE + 32 * BSTRIDE)   // 8448
#define STG 3
#define SMEM_BYTES   (STG * STAGE_FLOATS * 4)         // 101376

__device__ __forceinline__ int aswz(int r, int colf) {
    return r * ASTRIDE + ((((colf >> 2) ^ (r & 7)) << 2) | (colf & 3));
}

// ---------------------------------------------------------------------------
// cheb1 (tf32, split-K): raw partial S_h = sum_{m in half h} adj[n][m]*x[m][c].
// ALSO: fused adj column-sum partials AND bf16 conversion of adj (emitted from
// the staged fp32 tiles; each adj element visited exactly once across grid).
// ---------------------------------------------------------------------------
__global__ void __launch_bounds__(256, 2)
cheb1_kernel(const float* __restrict__ adj, const float* __restrict__ x,
             float* __restrict__ out0, float* __restrict__ out1) {
    extern __shared__ float sm[];

    int b       = blockIdx.y;
    int h       = blockIdx.z;
    int rowTile = blockIdx.x * 128;

    const float* adjB = adj + (size_t)b * N_SZ * N_SZ;
    const float* zB   = x + (size_t)b * NC;
    float*       oB   = (h == 0) ? (out0 + (size_t)b * ZBATCH)
                                 : (out1 + (size_t)b * NC);
    float*       prt  = g_part2 + (((size_t)b * 32 + blockIdx.x) * 8) * N_SZ;
    uint32_t*    awB  = g_adj16 + ((size_t)b * N_SZ + rowTile) * NPAIR;

    int tid  = threadIdx.x;
    int lane = tid & 31;
    int warp = tid >> 5;
    int wr = warp >> 2, wc = warp & 3;
    int g  = lane >> 2, tg = lane & 3;

    int ktBase = h * 64;

    float acc[4][4][4];
    #pragma unroll
    for (int i = 0; i < 4; i++)
        #pragma unroll
        for (int j = 0; j < 4; j++)
            #pragma unroll
            for (int v = 0; v < 4; v++) acc[i][j][v] = 0.f;

    auto stage = [&](int t) {
        float* As = sm + (t % STG) * STAGE_FLOATS;
        float* Bs = As + 128 * ASTRIDE;
        int k0 = (ktBase + t) * 32;
        #pragma unroll
        for (int it = 0; it < 4; it++) {
            int r = (tid >> 3) + it * 32;
            int q = tid & 7;
            cp16(As + r * ASTRIDE + ((q ^ (r & 7)) << 2),
                 adjB + (size_t)(rowTile + r) * N_SZ + k0 + q * 4);
        }
        #pragma unroll
        for (int it = 0; it < 4; it++) {
            int kr = (tid >> 5) + it * 8;
            int q  = (tid & 31) * 4;
            cp16(Bs + kr * BSTRIDE + q, zB + (size_t)(k0 + kr) * C_SZ + q);
        }
        cp_commit();
    };

    stage(0); stage(1);

    for (int kt = 0; kt < 64; kt++) {
        cp_wait<1>();
        __syncthreads();

        const float* As = sm + (kt % STG) * STAGE_FLOATS;
        const float* Bs = As + 128 * ASTRIDE;

        #pragma unroll
        for (int ks = 0; ks < 4; ks++) {
            int kb = ks * 8;
            int offA0 = ((((2 * ks)     ^ g) << 2) | tg);
            int offA1 = ((((2 * ks + 1) ^ g) << 2) | tg);
            uint32_t bf[4][2];
            #pragma unroll
            for (int ni = 0; ni < 4; ni++) {
                int col = wc * 32 + ni * 8 + g;
                bf[ni][0] = tf32_trunc(Bs[(kb + tg) * BSTRIDE + col]);
                bf[ni][1] = tf32_trunc(Bs[(kb + tg + 4) * BSTRIDE + col]);
            }
            #pragma unroll
            for (int mi = 0; mi < 4; mi++) {
                int r0 = wr * 64 + mi * 16 + g;
                uint32_t af[4];
                af[0] = tf32_trunc(As[(r0    ) * ASTRIDE + offA0]);
                af[1] = tf32_trunc(As[(r0 + 8) * ASTRIDE + offA0]);
                af[2] = tf32_trunc(As[(r0    ) * ASTRIDE + offA1]);
                af[3] = tf32_trunc(As[(r0 + 8) * ASTRIDE + offA1]);
                #pragma unroll
                for (int ni = 0; ni < 4; ni++)
                    mma_tf32(acc[mi][ni], af, bf[ni]);
            }
        }

        // fused adj colsum partials (warp: 16 rows, col = lane)
        {
            float cs = 0.f;
            #pragma unroll
            for (int r = 0; r < 16; r++) {
                int rr = warp * 16 + r;
                cs += As[aswz(rr, lane)];
            }
            prt[(size_t)warp * N_SZ + (ktBase + kt) * 32 + lane] = cs;
        }

        // fused bf16 conversion of this adj tile (pairs along k)
        {
            uint32_t* aw = awB + (size_t)(ktBase + kt) * 16;
            #pragma unroll
            for (int i = 0; i < 8; i++) {
                int pid = tid + i * 256;            // 0..2047
                int r = pid >> 4, pc = pid & 15;
                float v0 = As[aswz(r, pc * 2)];
                float v1 = As[aswz(r, pc * 2 + 1)];
                aw[(size_t)r * NPAIR + pc] = pack_bf16(v0, v1);
            }
        }

        if (kt + 2 < 64) stage(kt + 2);
        else             cp_commit();
    }

    #pragma unroll
    for (int mi = 0; mi < 4; mi++) {
        int r0 = rowTile + wr * 64 + mi * 16 + g;
        int r1 = r0 + 8;
        #pragma unroll
        for (int ni = 0; ni < 4; ni++) {
            int c0 = wc * 32 + ni * 8 + tg * 2;
            *(float2*)&oB[(size_t)r0 * C_SZ + c0] = make_float2(acc[mi][ni][0], acc[mi][ni][1]);
            *(float2*)&oB[(size_t)r1 * C_SZ + c0] = make_float2(acc[mi][ni][2], acc[mi][ni][3]);
        }
    }
}

// ---------------------------------------------------------------------------
// coef[b][m] = LR * (sum of 256 partials) - 1
// ---------------------------------------------------------------------------
__global__ void deg_reduce_kernel() {
    int i = blockIdx.x * blockDim.x + threadIdx.x;
    int b = i >> 12, m = i & 4095;
    float s = 0.f;
    #pragma unroll 8
    for (int j = 0; j < 256; j++)
        s += g_part2[((size_t)b * 256 + j) * N_SZ + m];
    g_coef[i] = LR * s - 1.0f;
}

// ---------------------------------------------------------------------------
// combine1: per pair-row (2m, 2m+1):
//   slice0 = x;  slice1 = coef*x - LR*(slice1 + Sp1);  z16 = packed bf16 Z1.
// ---------------------------------------------------------------------------
__global__ void combine1_kernel(const float* __restrict__ x) {
    int i   = blockIdx.x * blockDim.x + threadIdx.x;  // 0..262143
    int b   = i >> 16;                                // 65536 items/batch
    int rem = i & 65535;
    int m2  = rem >> 5;                               // pair row
    int cq  = (rem & 31) * 4;                         // col group

    size_t r0 = 2 * (size_t)m2, r1 = r0 + 1;
    float cf0 = g_coef[b * N_SZ + r0];
    float cf1 = g_coef[b * N_SZ + r1];

    const float* xB = x + (size_t)b * NC;
    float* zb = g_Z + (size_t)b * ZBATCH;

    float4 x0 = *(const float4*)(xB + r0 * C_SZ + cq);
    float4 x1 = *(const float4*)(xB + r1 * C_SZ + cq);
    float4 p0 = *(const float4*)(g_Sp1 + (size_t)b * NC + r0 * C_SZ + cq);
    float4 p1 = *(const float4*)(g_Sp1 + (size_t)b * NC + r1 * C_SZ + cq);
    float4 s0 = *(const float4*)(zb + NC + r0 * C_SZ + cq);
    float4 s1 = *(const float4*)(zb + NC + r1 * C_SZ + cq);

    float4 o0, o1;
    o0.x = cf0 * x0.x - LR * (s0.x + p0.x);
    o0.y = cf0 * x0.y - LR * (s0.y + p0.y);
    o0.z = cf0 * x0.z - LR * (s0.z + p0.z);
    o0.w = cf0 * x0.w - LR * (s0.w + p0.w);
    o1.x = cf1 * x1.x - LR * (s1.x + p1.x);
    o1.y = cf1 * x1.y - LR * (s1.y + p1.y);
    o1.z = cf1 * x1.z - LR * (s1.z + p1.z);
    o1.w = cf1 * x1.w - LR * (s1.w + p1.w);

    *(float4*)(zb + r0 * C_SZ + cq) = x0;             // slice0 = x
    *(float4*)(zb + r1 * C_SZ + cq) = x1;
    *(float4*)(zb + NC + r0 * C_SZ + cq) = o0;        // slice1 = Z1
    *(float4*)(zb + NC + r1 * C_SZ + cq) = o1;

    uint4 pk;
    pk.x = pack_bf16(o0.x, o1.x);
    pk.y = pack_bf16(o0.y, o1.y);
    pk.z = pack_bf16(o0.z, o1.z);
    pk.w = pack_bf16(o0.w, o1.w);
    *(uint4*)(g_z16 + ((size_t)b * NPAIR + m2) * C_SZ + cq) = pk;
}

// ---------------------------------------------------------------------------
// cheb2 (bf16 m16n8k16, split-K): raw partial S_h = adj@Z1 over half h.
// A from g_adj16 (pure cp.async), B from g_z16 (pure cp.async).
// A smem: [128 rows][20-word stride] pairs; B smem: [16 pairs][136] words.
// ---------------------------------------------------------------------------
#define A2STRIDE 20
#define B2STRIDE 136
#define STAGE2_WORDS (128 * A2STRIDE + 16 * B2STRIDE)  // 4736
#define SMEM2_BYTES  (STG * STAGE2_WORDS * 4)          // 56832

__global__ void __launch_bounds__(256, 2)
cheb2_kernel(float* __restrict__ out0, float* __restrict__ out1) {
    extern __shared__ uint32_t sw[];

    int b       = blockIdx.y;
    int h       = blockIdx.z;
    int rowTile = blockIdx.x * 128;

    const uint32_t* awB = g_adj16 + ((size_t)b * N_SZ + rowTile) * NPAIR;
    const uint32_t* zwB = g_z16 + (size_t)b * NPAIR * C_SZ;
    float* oB = (h == 0) ? (out0 + (size_t)b * ZBATCH)
                         : (out1 + (size_t)b * NC);

    int tid  = threadIdx.x;
    int lane = tid & 31;
    int warp = tid >> 5;
    int wr = warp >> 2, wc = warp & 3;
    int g  = lane >> 2, tg = lane & 3;

    int ktBase = h * 64;

    float acc[4][4][4];
    #pragma unroll
    for (int i = 0; i < 4; i++)
        #pragma unroll
        for (int j = 0; j < 4; j++)
            #pragma unroll
            for (int v = 0; v < 4; v++) acc[i][j][v] = 0.f;

    auto stage = [&](int t) {
        uint32_t* As = sw + (t % STG) * STAGE2_WORDS;
        uint32_t* Bs = As + 128 * A2STRIDE;
        int p0 = (ktBase + t) * 16;                 // pair offset
        #pragma unroll
        for (int i = 0; i < 2; i++) {
            int cid = tid + i * 256;                // 0..511
            int r = cid >> 2, q = cid & 3;          // row, 16B chunk
            cp16(As + r * A2STRIDE + q * 4, awB + (size_t)r * NPAIR + p0 + q * 4);
        }
        #pragma unroll
        for (int i = 0; i < 2; i++) {
            int cid = tid + i * 256;
            int kr = cid >> 5, q = (cid & 31) * 4;  // pair row, col chunk
            cp16(Bs + kr * B2STRIDE + q, zwB + (size_t)(p0 + kr) * C_SZ + q);
        }
        cp_commit();
    };

    stage(0); stage(1);

    for (int kt = 0; kt < 64; kt++) {
        cp_wait<1>();
        __syncthreads();

        const uint32_t* As = sw + (kt % STG) * STAGE2_WORDS;
        const uint32_t* Bs = As + 128 * A2STRIDE;

        #pragma unroll
        for (int ks = 0; ks < 2; ks++) {            // two k16 steps per k32 tile
            int pb = ks * 8;
            uint32_t bf[4][2];
            #pragma unroll
            for (int ni = 0; ni < 4; ni++) {
                int col = wc * 32 + ni * 8 + g;
                bf[ni][0] = Bs[(pb + tg) * B2STRIDE + col];
                bf[ni][1] = Bs[(pb + tg + 4) * B2STRIDE + col];
            }
            #pragma unroll
            for (int mi = 0; mi < 4; mi++) {
                int r0 = wr * 64 + mi * 16 + g;
                uint32_t af[4];
                af[0] = As[(r0    ) * A2STRIDE + pb + tg];
                af[1] = As[(r0 + 8) * A2STRIDE + pb + tg];
                af[2] = As[(r0    ) * A2STRIDE + pb + tg + 4];
                af[3] = As[(r0 + 8) * A2STRIDE + pb + tg + 4];
                #pragma unroll
                for (int ni = 0; ni < 4; ni++)
                    mma_bf16(acc[mi][ni], af, bf[ni]);
            }
        }

        if (kt + 2 < 64) stage(kt + 2);
        else             cp_commit();
    }

    #pragma unroll
    for (int mi = 0; mi < 4; mi++) {
        int r0 = rowTile + wr * 64 + mi * 16 + g;
        int r1 = r0 + 8;
        #pragma unroll
        for (int ni = 0; ni < 4; ni++) {
            int c0 = wc * 32 + ni * 8 + tg * 2;
            *(float2*)&oB[(size_t)r0 * C_SZ + c0] = make_float2(acc[mi][ni][0], acc[mi][ni][1]);
            *(float2*)&oB[(size_t)r1 * C_SZ + c0] = make_float2(acc[mi][ni][2], acc[mi][ni][3]);
        }
    }
}

// ---------------------------------------------------------------------------
// combine2: slice2 = 2*coef*z1 - 2*LR*(slice2 + Sp1) - x
// ---------------------------------------------------------------------------
__global__ void combine2_kernel(const float* __restrict__ x) {
    size_t i   = (size_t)blockIdx.x * blockDim.x + threadIdx.x;
    size_t b   = i / (NC / 4);
    size_t rem = i % (NC / 4);
    size_t row = rem >> 5;
    float cf2 = 2.0f * g_coef[b * N_SZ + row];
    float4 xv = ((const float4*)x)[i];
    float4 s1 = ((const float4*)g_Sp1)[i];
    const float4* z1 = (const float4*)g_Z + b * (ZBATCH / 4) + NC / 4 + rem;
    float4* z2 = (float4*)g_Z + b * (ZBATCH / 4) + 2 * (NC / 4) + rem;
    float4 zv = *z1;
    float4 s0 = *z2;
    float4 o;
    o.x = cf2 * zv.x - 2.0f * LR * (s0.x + s1.x) - xv.x;
    o.y = cf2 * zv.y - 2.0f * LR * (s0.y + s1.y) - xv.y;
    o.z = cf2 * zv.z - 2.0f * LR * (s0.z + s1.z) - xv.z;
    o.w = cf2 * zv.w - 2.0f * LR * (s0.w + s1.w) - xv.w;
    *z2 = o;
}

// ---------------------------------------------------------------------------
// Final linear via 3xTF32 (hi/lo mantissa split); W transpose in B-staging.
// ---------------------------------------------------------------------------
__global__ void __launch_bounds__(256, 1)
out_gemm_kernel(const float* __restrict__ W, float* __restrict__ out) {
    extern __shared__ float sm[];
    int rowTile = blockIdx.x * 128;

    int tid  = threadIdx.x;
    int lane = tid & 31;
    int warp = tid >> 5;
    int wr = warp >> 2, wc = warp & 3;
    int g  = lane >> 2, tg = lane & 3;

    float acc[4][4][4];
    #pragma unroll
    for (int i = 0; i < 4; i++)
        #pragma unroll
        for (int j = 0; j < 4; j++)
            #pragma unroll
            for (int v = 0; v < 4; v++) acc[i][j][v] = 0.f;

    auto stage = [&](int t) {
        float* As = sm + (t % STG) * STAGE_FLOATS;
        float* Bs = As + 128 * ASTRIDE;
        int k0 = t * 32;
        #pragma unroll
        for (int it = 0; it < 4; it++) {
            int r = (tid >> 3) + it * 32;
            int q = tid & 7;
            cp16(As + r * ASTRIDE + ((q ^ (r & 7)) << 2),
                 g_Z + (size_t)(rowTile + r) * KC + k0 + q * 4);
        }
        cp_commit();
        int o  = tid >> 1;
        int kq = (tid & 1) * 16;
        #pragma unroll
        for (int j = 0; j < 4; j++) {
            float4 v = *(const float4*)(W + (size_t)o * KC + k0 + kq + j * 4);
            Bs[(kq + j * 4 + 0) * BSTRIDE + o] = v.x;
            Bs[(kq + j * 4 + 1) * BSTRIDE + o] = v.y;
            Bs[(kq + j * 4 + 2) * BSTRIDE + o] = v.z;
            Bs[(kq + j * 4 + 3) * BSTRIDE + o] = v.w;
        }
    };

    stage(0); stage(1);

    for (int kt = 0; kt < 12; kt++) {
        cp_wait<1>();
        __syncthreads();

        const float* As = sm + (kt % STG) * STAGE_FLOATS;
        const float* Bs = As + 128 * ASTRIDE;

        #pragma unroll
        for (int ks = 0; ks < 4; ks++) {
            int kb = ks * 8;
            int offA0 = ((((2 * ks)     ^ g) << 2) | tg);
            int offA1 = ((((2 * ks + 1) ^ g) << 2) | tg);
            uint32_t bh[4][2], bl[4][2];
            #pragma unroll
            for (int ni = 0; ni < 4; ni++) {
                int col = wc * 32 + ni * 8 + g;
                float v0 = Bs[(kb + tg) * BSTRIDE + col];
                float v1 = Bs[(kb + tg + 4) * BSTRIDE + col];
                bh[ni][0] = tf32_trunc(v0);
                bh[ni][1] = tf32_trunc(v1);
                bl[ni][0] = tf32_trunc(v0 - __uint_as_float(bh[ni][0]));
                bl[ni][1] = tf32_trunc(v1 - __uint_as_float(bh[ni][1]));
            }
            #pragma unroll
            for (int mi = 0; mi < 4; mi++) {
                int r0 = wr * 64 + mi * 16 + g;
                float a0 = As[(r0    ) * ASTRIDE + offA0];
                float a1 = As[(r0 + 8) * ASTRIDE + offA0];
                float a2 = As[(r0    ) * ASTRIDE + offA1];
                float a3 = As[(r0 + 8) * ASTRIDE + offA1];
                uint32_t ah[4], al[4];
                ah[0] = tf32_trunc(a0); ah[1] = tf32_trunc(a1);
                ah[2] = tf32_trunc(a2); ah[3] = tf32_trunc(a3);
                al[0] = tf32_trunc(a0 - __uint_as_float(ah[0]));
                al[1] = tf32_trunc(a1 - __uint_as_float(ah[1]));
                al[2] = tf32_trunc(a2 - __uint_as_float(ah[2]));
                al[3] = tf32_trunc(a3 - __uint_as_float(ah[3]));
                #pragma unroll
                for (int ni = 0; ni < 4; ni++) {
                    mma_tf32(acc[mi][ni], ah, bh[ni]);
                    mma_tf32(acc[mi][ni], ah, bl[ni]);
                    mma_tf32(acc[mi][ni], al, bh[ni]);
                }
            }
        }

        if (kt + 2 < 12) stage(kt + 2);
        else             cp_commit();
    }

    #pragma unroll
    for (int mi = 0; mi < 4; mi++) {
        size_t r0 = (size_t)rowTile + wr * 64 + mi * 16 + g;
        size_t r1 = r0 + 8;
        #pragma unroll
        for (int ni = 0; ni < 4; ni++) {
            int c0 = wc * 32 + ni * 8 + tg * 2;
            *(float2*)&out[r0 * C_SZ + c0] = make_float2(acc[mi][ni][0], acc[mi][ni][1]);
            *(float2*)&out[r1 * C_SZ + c0] = make_float2(acc[mi][ni][2], acc[mi][ni][3]);
        }
    }
}

// ---------------------------------------------------------------------------
extern "C" void kernel_launch(void* const* d_in, const int* in_sizes, int n_in,
                              void* d_out, int out_size) {
    const float* x   = nullptr;
    const float* adj = nullptr;
    const float* W   = nullptr;
    for (int i = 0; i < n_in; i++) {
        long long sz = in_sizes[i];
        if (sz == (long long)B_SZ * N_SZ * N_SZ)      adj = (const float*)d_in[i];
        else if (sz == (long long)B_SZ * N_SZ * C_SZ) x   = (const float*)d_in[i];
        else                                          W   = (const float*)d_in[i];
    }
    float* out = (float*)d_out;

    cudaFuncSetAttribute(cheb1_kernel,
                         cudaFuncAttributeMaxDynamicSharedMemorySize, SMEM_BYTES);
    cudaFuncSetAttribute(cheb2_kernel,
                         cudaFuncAttributeMaxDynamicSharedMemorySize, SMEM2_BYTES);
    cudaFuncSetAttribute(out_gemm_kernel,
                         cudaFuncAttributeMaxDynamicSharedMemorySize, SMEM_BYTES);

    float* g_Z_ptr;    cudaGetSymbolAddress((void**)&g_Z_ptr, g_Z);
    float* g_Sp1_ptr;  cudaGetSymbolAddress((void**)&g_Sp1_ptr, g_Sp1);

    // cheb1 (tf32): h=0 -> slice1 raw, h=1 -> Sp1; fused colsums + adj->bf16
    cheb1_kernel<<<dim3(32, B_SZ, 2), 256, SMEM_BYTES>>>(
        adj, x, g_Z_ptr + NC, g_Sp1_ptr);
    deg_reduce_kernel<<<(B_SZ * N_SZ) / 256, 256>>>();
    combine1_kernel<<<1024, 256>>>(x);

    // cheb2 (bf16): h=0 -> slice2 raw, h=1 -> Sp1
    cheb2_kernel<<<dim3(32, B_SZ, 2), 256, SMEM2_BYTES>>>(
        g_Z_ptr + 2 * NC, g_Sp1_ptr);
    combine2_kernel<<<(unsigned)((B_SZ * NC / 4) / 256), 256>>>(x);

    out_gemm_kernel<<<(B_SZ * N_SZ) / 128, 256, SMEM_BYTES>>>(W, out);
}

// round 16
// speedup vs baseline: 4.0640x; 1.0061x over previous
#include <cuda_runtime.h>
#include <cstdint>
#include <cstddef>

#define B_SZ 4
#define N_SZ 4096
#define C_SZ 128
#define KCH  3
#define KC   (KCH * C_SZ)                       // 384
#define NC   ((size_t)N_SZ * C_SZ)              // 524288
#define ZBATCH ((size_t)KCH * N_SZ * C_SZ)      // 1572864
#define NPAIR 2048                              // N_SZ/2 bf16 pairs

static constexpr float LR = 2.0f / (2.0f + 1e-6f);

// Scratch (device globals: no runtime allocation allowed)
__device__ float    g_Z[(size_t)B_SZ * KCH * N_SZ * C_SZ];   // 24 MB
__device__ float    g_Sp1[(size_t)B_SZ * N_SZ * C_SZ];       // split-K h=1 partial (8 MB)
__device__ float    g_part2[(size_t)B_SZ * 32 * 4 * 1024];   // colsum partials (2 MB)
__device__ float    g_coef[B_SZ * N_SZ];                     // lr*deg - 1
__device__ uint32_t g_adj16[(size_t)B_SZ * N_SZ * NPAIR];    // adj bf16x2-packed (128 MB)
__device__ uint32_t g_x16[(size_t)B_SZ * NPAIR * C_SZ];      // x bf16, m-pair packed (4 MB)
__device__ uint32_t g_z16[(size_t)B_SZ * NPAIR * C_SZ];      // Z1 bf16, m-pair packed (4 MB)

// ---------------------------------------------------------------------------
// helpers
// ---------------------------------------------------------------------------
__device__ __forceinline__ unsigned smem_u32(const void* p) {
    return (unsigned)__cvta_generic_to_shared(p);
}
__device__ __forceinline__ void cp16(void* dst, const void* src) {
    asm volatile("cp.async.cg.shared.global [%0], [%1], 16;\n"
                 :: "r"(smem_u32(dst)), "l"(src));
}
__device__ __forceinline__ void cp_commit() { asm volatile("cp.async.commit_group;\n"); }
template <int Nn>
__device__ __forceinline__ void cp_wait() {
    asm volatile("cp.async.wait_group %0;\n" :: "n"(Nn));
}
__device__ __forceinline__ uint32_t tf32_trunc(float x) {
    return __float_as_uint(x) & 0xFFFFE000u;
}
// pack two floats into bf16x2 (lo = first in k order, hi = second)
__device__ __forceinline__ uint32_t pack_bf16(float lo, float hi) {
    uint32_t d;
    asm("cvt.rn.bf16x2.f32 %0, %1, %2;" : "=r"(d) : "f"(hi), "f"(lo));
    return d;
}
__device__ __forceinline__ void mma_tf32(float* d, const uint32_t* a, const uint32_t* b) {
    asm volatile(
        "mma.sync.aligned.m16n8k8.row.col.f32.tf32.tf32.f32 "
        "{%0,%1,%2,%3}, {%4,%5,%6,%7}, {%8,%9}, {%0,%1,%2,%3};\n"
        : "+f"(d[0]), "+f"(d[1]), "+f"(d[2]), "+f"(d[3])
        : "r"(a[0]), "r"(a[1]), "r"(a[2]), "r"(a[3]), "r"(b[0]), "r"(b[1]));
}
__device__ __forceinline__ void mma_bf16(float* d, const uint32_t* a, const uint32_t* b) {
    asm volatile(
        "mma.sync.aligned.m16n8k16.row.col.f32.bf16.bf16.f32 "
        "{%0,%1,%2,%3}, {%4,%5,%6,%7}, {%8,%9}, {%0,%1,%2,%3};\n"
        : "+f"(d[0]), "+f"(d[1]), "+f"(d[2]), "+f"(d[3])
        : "r"(a[0]), "r"(a[1]), "r"(a[2]), "r"(a[3]), "r"(b[0]), "r"(b[1]));
}

// ---------------------------------------------------------------------------
// prep: single streaming pass over adj.
//   - writes bf16x2-packed adj (pairs along k/columns)
//   - writes fp32 column-sum partials (per 128-row chunk, per 1024-col group)
// grid (4 colgroups, 32 rowchunks, B), block 256. Pure float4 streaming.
// ---------------------------------------------------------------------------
__global__ void __launch_bounds__(256)
prep_kernel(const float* __restrict__ adj) {
    int b = blockIdx.z, rc = blockIdx.y, cg = blockIdx.x;
    int c4 = threadIdx.x;                       // col group of 4 within 1024
    const float* a = adj + (size_t)b * N_SZ * N_SZ
                   + (size_t)rc * 128 * N_SZ + cg * 1024 + c4 * 4;
    uint32_t* aw = g_adj16 + ((size_t)b * N_SZ + (size_t)rc * 128) * NPAIR
                 + cg * 512 + c4 * 2;
    float4 s = make_float4(0.f, 0.f, 0.f, 0.f);
    #pragma unroll 8
    for (int r = 0; r < 128; r++) {
        float4 v = *(const float4*)(a + (size_t)r * N_SZ);
        s.x += v.x; s.y += v.y; s.z += v.z; s.w += v.w;
        uint2 p;
        p.x = pack_bf16(v.x, v.y);
        p.y = pack_bf16(v.z, v.w);
        *(uint2*)(aw + (size_t)r * NPAIR) = p;
    }
    float* pp = g_part2 + ((((size_t)b * 32 + rc) * 4 + cg) * 1024) + c4 * 4;
    pp[0] = s.x; pp[1] = s.y; pp[2] = s.z; pp[3] = s.w;
}

// ---------------------------------------------------------------------------
// coef[b][m] = LR * (sum of 32 row-chunk partials) - 1
// ---------------------------------------------------------------------------
__global__ void deg_reduce_kernel() {
    int i = blockIdx.x * blockDim.x + threadIdx.x;   // b*4096 + m
    int b = i >> 12, m = i & 4095;
    int cg = m >> 10, c = m & 1023;
    float s = 0.f;
    #pragma unroll
    for (int rc = 0; rc < 32; rc++)
        s += g_part2[(((size_t)b * 32 + rc) * 4 + cg) * 1024 + c];
    g_coef[i] = LR * s - 1.0f;
}

// ---------------------------------------------------------------------------
// xpack: x -> bf16, m-pair packed: x16[(b*NPAIR+m2)*C + c] = pack(x[2m2][c], x[2m2+1][c])
// ---------------------------------------------------------------------------
__global__ void xpack_kernel(const float* __restrict__ x) {
    int i   = blockIdx.x * blockDim.x + threadIdx.x;  // 0..262143
    int b   = i >> 16;
    int rem = i & 65535;
    int m2  = rem >> 5;
    int cq  = (rem & 31) * 4;
    const float* xB = x + (size_t)b * NC;
    float4 v0 = *(const float4*)(xB + (size_t)(2 * m2) * C_SZ + cq);
    float4 v1 = *(const float4*)(xB + (size_t)(2 * m2 + 1) * C_SZ + cq);
    uint4 pk;
    pk.x = pack_bf16(v0.x, v1.x);
    pk.y = pack_bf16(v0.y, v1.y);
    pk.z = pack_bf16(v0.z, v1.z);
    pk.w = pack_bf16(v0.w, v1.w);
    *(uint4*)(g_x16 + ((size_t)b * NPAIR + m2) * C_SZ + cq) = pk;
}

// ---------------------------------------------------------------------------
// Generic bf16 split-K GEMM: raw partial S_h[n][c] = sum_{m in half h}
// adj[n][m] * B[m][c];  A = g_adj16, B = bw (m-pair packed bf16).
// grid (32 rowtiles, B, 2 halves), 2 CTAs/SM.
// ---------------------------------------------------------------------------
#define STG 3
#define A2STRIDE 20
#define B2STRIDE 136
#define STAGE2_WORDS (128 * A2STRIDE + 16 * B2STRIDE)  // 4736
#define SMEM2_BYTES  (STG * STAGE2_WORDS * 4)          // 56832

__global__ void __launch_bounds__(256, 2)
cheb16_kernel(const uint32_t* __restrict__ bw,
              float* __restrict__ out0, size_t o0Stride,
              float* __restrict__ out1, size_t o1Stride) {
    extern __shared__ uint32_t sw[];

    int b       = blockIdx.y;
    int h       = blockIdx.z;
    int rowTile = blockIdx.x * 128;

    const uint32_t* awB = g_adj16 + ((size_t)b * N_SZ + rowTile) * NPAIR;
    const uint32_t* zwB = bw + (size_t)b * NPAIR * C_SZ;
    float* oB = (h == 0) ? (out0 + (size_t)b * o0Stride)
                         : (out1 + (size_t)b * o1Stride);

    int tid  = threadIdx.x;
    int lane = tid & 31;
    int warp = tid >> 5;
    int wr = warp >> 2, wc = warp & 3;
    int g  = lane >> 2, tg = lane & 3;

    int ktBase = h * 64;

    float acc[4][4][4];
    #pragma unroll
    for (int i = 0; i < 4; i++)
        #pragma unroll
        for (int j = 0; j < 4; j++)
            #pragma unroll
            for (int v = 0; v < 4; v++) acc[i][j][v] = 0.f;

    auto stage = [&](int t) {
        uint32_t* As = sw + (t % STG) * STAGE2_WORDS;
        uint32_t* Bs = As + 128 * A2STRIDE;
        int p0 = (ktBase + t) * 16;                 // pair offset
        #pragma unroll
        for (int i = 0; i < 2; i++) {
            int cid = tid + i * 256;                // 0..511
            int r = cid >> 2, q = cid & 3;          // row, 16B chunk
            cp16(As + r * A2STRIDE + q * 4, awB + (size_t)r * NPAIR + p0 + q * 4);
        }
        #pragma unroll
        for (int i = 0; i < 2; i++) {
            int cid = tid + i * 256;
            int kr = cid >> 5, q = (cid & 31) * 4;  // pair row, col chunk
            cp16(Bs + kr * B2STRIDE + q, zwB + (size_t)(p0 + kr) * C_SZ + q);
        }
        cp_commit();
    };

    stage(0); stage(1);

    for (int kt = 0; kt < 64; kt++) {
        cp_wait<1>();
        __syncthreads();

        const uint32_t* As = sw + (kt % STG) * STAGE2_WORDS;
        const uint32_t* Bs = As + 128 * A2STRIDE;

        #pragma unroll
        for (int ks = 0; ks < 2; ks++) {            // two k16 steps per k32 tile
            int pb = ks * 8;
            uint32_t bf[4][2];
            #pragma unroll
            for (int ni = 0; ni < 4; ni++) {
                int col = wc * 32 + ni * 8 + g;
                bf[ni][0] = Bs[(pb + tg) * B2STRIDE + col];
                bf[ni][1] = Bs[(pb + tg + 4) * B2STRIDE + col];
            }
            #pragma unroll
            for (int mi = 0; mi < 4; mi++) {
                int r0 = wr * 64 + mi * 16 + g;
                uint32_t af[4];
                af[0] = As[(r0    ) * A2STRIDE + pb + tg];
                af[1] = As[(r0 + 8) * A2STRIDE + pb + tg];
                af[2] = As[(r0    ) * A2STRIDE + pb + tg + 4];
                af[3] = As[(r0 + 8) * A2STRIDE + pb + tg + 4];
                #pragma unroll
                for (int ni = 0; ni < 4; ni++)
                    mma_bf16(acc[mi][ni], af, bf[ni]);
            }
        }

        if (kt + 2 < 64) stage(kt + 2);
        else             cp_commit();
    }

    #pragma unroll
    for (int mi = 0; mi < 4; mi++) {
        int r0 = rowTile + wr * 64 + mi * 16 + g;
        int r1 = r0 + 8;
        #pragma unroll
        for (int ni = 0; ni < 4; ni++) {
            int c0 = wc * 32 + ni * 8 + tg * 2;
            *(float2*)&oB[(size_t)r0 * C_SZ + c0] = make_float2(acc[mi][ni][0], acc[mi][ni][1]);
            *(float2*)&oB[(size_t)r1 * C_SZ + c0] = make_float2(acc[mi][ni][2], acc[mi][ni][3]);
        }
    }
}

// ---------------------------------------------------------------------------
// combine1: per pair-row (2m, 2m+1):
//   slice0 = x;  slice1 = coef*x - LR*(slice1 + Sp1);  z16 = packed bf16 Z1.
// ---------------------------------------------------------------------------
__global__ void combine1_kernel(const float* __restrict__ x) {
    int i   = blockIdx.x * blockDim.x + threadIdx.x;  // 0..262143
    int b   = i >> 16;
    int rem = i & 65535;
    int m2  = rem >> 5;
    int cq  = (rem & 31) * 4;

    size_t r0 = 2 * (size_t)m2, r1 = r0 + 1;
    float cf0 = g_coef[b * N_SZ + r0];
    float cf1 = g_coef[b * N_SZ + r1];

    const float* xB = x + (size_t)b * NC;
    float* zb = g_Z + (size_t)b * ZBATCH;

    float4 x0 = *(const float4*)(xB + r0 * C_SZ + cq);
    float4 x1 = *(const float4*)(xB + r1 * C_SZ + cq);
    float4 p0 = *(const float4*)(g_Sp1 + (size_t)b * NC + r0 * C_SZ + cq);
    float4 p1 = *(const float4*)(g_Sp1 + (size_t)b * NC + r1 * C_SZ + cq);
    float4 s0 = *(const float4*)(zb + NC + r0 * C_SZ + cq);
    float4 s1 = *(const float4*)(zb + NC + r1 * C_SZ + cq);

    float4 o0, o1;
    o0.x = cf0 * x0.x - LR * (s0.x + p0.x);
    o0.y = cf0 * x0.y - LR * (s0.y + p0.y);
    o0.z = cf0 * x0.z - LR * (s0.z + p0.z);
    o0.w = cf0 * x0.w - LR * (s0.w + p0.w);
    o1.x = cf1 * x1.x - LR * (s1.x + p1.x);
    o1.y = cf1 * x1.y - LR * (s1.y + p1.y);
    o1.z = cf1 * x1.z - LR * (s1.z + p1.z);
    o1.w = cf1 * x1.w - LR * (s1.w + p1.w);

    *(float4*)(zb + r0 * C_SZ + cq) = x0;             // slice0 = x
    *(float4*)(zb + r1 * C_SZ + cq) = x1;
    *(float4*)(zb + NC + r0 * C_SZ + cq) = o0;        // slice1 = Z1
    *(float4*)(zb + NC + r1 * C_SZ + cq) = o1;

    uint4 pk;
    pk.x = pack_bf16(o0.x, o1.x);
    pk.y = pack_bf16(o0.y, o1.y);
    pk.z = pack_bf16(o0.z, o1.z);
    pk.w = pack_bf16(o0.w, o1.w);
    *(uint4*)(g_z16 + ((size_t)b * NPAIR + m2) * C_SZ + cq) = pk;
}

// ---------------------------------------------------------------------------
// combine2: slice2 = 2*coef*z1 - 2*LR*(slice2 + Sp1) - x
// ---------------------------------------------------------------------------
__global__ void combine2_kernel(const float* __restrict__ x) {
    size_t i   = (size_t)blockIdx.x * blockDim.x + threadIdx.x;
    size_t b   = i / (NC / 4);
    size_t rem = i % (NC / 4);
    size_t row = rem >> 5;
    float cf2 = 2.0f * g_coef[b * N_SZ + row];
    float4 xv = ((const float4*)x)[i];
    float4 s1 = ((const float4*)g_Sp1)[i];
    const float4* z1 = (const float4*)g_Z + b * (ZBATCH / 4) + NC / 4 + rem;
    float4* z2 = (float4*)g_Z + b * (ZBATCH / 4) + 2 * (NC / 4) + rem;
    float4 zv = *z1;
    float4 s0 = *z2;
    float4 o;
    o.x = cf2 * zv.x - 2.0f * LR * (s0.x + s1.x) - xv.x;
    o.y = cf2 * zv.y - 2.0f * LR * (s0.y + s1.y) - xv.y;
    o.z = cf2 * zv.z - 2.0f * LR * (s0.z + s1.z) - xv.z;
    o.w = cf2 * zv.w - 2.0f * LR * (s0.w + s1.w) - xv.w;
    *z2 = o;
}

// ---------------------------------------------------------------------------
// Final linear via 3xTF32 (hi/lo mantissa split); W transpose in B-staging.
// ---------------------------------------------------------------------------
#define ASTRIDE 32
#define BSTRIDE 136
#define STAGE_FLOATS (128 * ASTRIDE + 32 * BSTRIDE)   // 8448
#define SMEM_BYTES   (STG * STAGE_FLOATS * 4)         // 101376

__global__ void __launch_bounds__(256, 1)
out_gemm_kernel(const float* __restrict__ W, float* __restrict__ out) {
    extern __shared__ float sm[];
    int rowTile = blockIdx.x * 128;

    int tid  = threadIdx.x;
    int lane = tid & 31;
    int warp = tid >> 5;
    int wr = warp >> 2, wc = warp & 3;
    int g  = lane >> 2, tg = lane & 3;

    float acc[4][4][4];
    #pragma unroll
    for (int i = 0; i < 4; i++)
        #pragma unroll
        for (int j = 0; j < 4; j++)
            #pragma unroll
            for (int v = 0; v < 4; v++) acc[i][j][v] = 0.f;

    auto stage = [&](int t) {
        float* As = sm + (t % STG) * STAGE_FLOATS;
        float* Bs = As + 128 * ASTRIDE;
        int k0 = t * 32;
        #pragma unroll
        for (int it = 0; it < 4; it++) {
            int r = (tid >> 3) + it * 32;
            int q = tid & 7;
            cp16(As + r * ASTRIDE + ((q ^ (r & 7)) << 2),
                 g_Z + (size_t)(rowTile + r) * KC + k0 + q * 4);
        }
        cp_commit();
        int o  = tid >> 1;
        int kq = (tid & 1) * 16;
        #pragma unroll
        for (int j = 0; j < 4; j++) {
            float4 v = *(const float4*)(W + (size_t)o * KC + k0 + kq + j * 4);
            Bs[(kq + j * 4 + 0) * BSTRIDE + o] = v.x;
            Bs[(kq + j * 4 + 1) * BSTRIDE + o] = v.y;
            Bs[(kq + j * 4 + 2) * BSTRIDE + o] = v.z;
            Bs[(kq + j * 4 + 3) * BSTRIDE + o] = v.w;
        }
    };

    stage(0); stage(1);

    for (int kt = 0; kt < 12; kt++) {
        cp_wait<1>();
        __syncthreads();

        const float* As = sm + (kt % STG) * STAGE_FLOATS;
        const float* Bs = As + 128 * ASTRIDE;

        #pragma unroll
        for (int ks = 0; ks < 4; ks++) {
            int kb = ks * 8;
            int offA0 = ((((2 * ks)     ^ g) << 2) | tg);
            int offA1 = ((((2 * ks + 1) ^ g) << 2) | tg);
            uint32_t bh[4][2], bl[4][2];
            #pragma unroll
            for (int ni = 0; ni < 4; ni++) {
                int col = wc * 32 + ni * 8 + g;
                float v0 = Bs[(kb + tg) * BSTRIDE + col];
                float v1 = Bs[(kb + tg + 4) * BSTRIDE + col];
                bh[ni][0] = tf32_trunc(v0);
                bh[ni][1] = tf32_trunc(v1);
                bl[ni][0] = tf32_trunc(v0 - __uint_as_float(bh[ni][0]));
                bl[ni][1] = tf32_trunc(v1 - __uint_as_float(bh[ni][1]));
            }
            #pragma unroll
            for (int mi = 0; mi < 4; mi++) {
                int r0 = wr * 64 + mi * 16 + g;
                float a0 = As[(r0    ) * ASTRIDE + offA0];
                float a1 = As[(r0 + 8) * ASTRIDE + offA0];
                float a2 = As[(r0    ) * ASTRIDE + offA1];
                float a3 = As[(r0 + 8) * ASTRIDE + offA1];
                uint32_t ah[4], al[4];
                ah[0] = tf32_trunc(a0); ah[1] = tf32_trunc(a1);
                ah[2] = tf32_trunc(a2); ah[3] = tf32_trunc(a3);
                al[0] = tf32_trunc(a0 - __uint_as_float(ah[0]));
                al[1] = tf32_trunc(a1 - __uint_as_float(ah[1]));
                al[2] = tf32_trunc(a2 - __uint_as_float(ah[2]));
                al[3] = tf32_trunc(a3 - __uint_as_float(ah[3]));
                #pragma unroll
                for (int ni = 0; ni < 4; ni++) {
                    mma_tf32(acc[mi][ni], ah, bh[ni]);
                    mma_tf32(acc[mi][ni], ah, bl[ni]);
                    mma_tf32(acc[mi][ni], al, bh[ni]);
                }
            }
        }

        if (kt + 2 < 12) stage(kt + 2);
        else             cp_commit();
    }

    #pragma unroll
    for (int mi = 0; mi < 4; mi++) {
        size_t r0 = (size_t)rowTile + wr * 64 + mi * 16 + g;
        size_t r1 = r0 + 8;
        #pragma unroll
        for (int ni = 0; ni < 4; ni++) {
            int c0 = wc * 32 + ni * 8 + tg * 2;
            *(float2*)&out[r0 * C_SZ + c0] = make_float2(acc[mi][ni][0], acc[mi][ni][1]);
            *(float2*)&out[r1 * C_SZ + c0] = make_float2(acc[mi][ni][2], acc[mi][ni][3]);
        }
    }
}

// ---------------------------------------------------------------------------
extern "C" void kernel_launch(void* const* d_in, const int* in_sizes, int n_in,
                              void* d_out, int out_size) {
    const float* x   = nullptr;
    const float* adj = nullptr;
    const float* W   = nullptr;
    for (int i = 0; i < n_in; i++) {
        long long sz = in_sizes[i];
        if (sz == (long long)B_SZ * N_SZ * N_SZ)      adj = (const float*)d_in[i];
        else if (sz == (long long)B_SZ * N_SZ * C_SZ) x   = (const float*)d_in[i];
        else                                          W   = (const float*)d_in[i];
    }
    float* out = (float*)d_out;

    cudaFuncSetAttribute(cheb16_kernel,
                         cudaFuncAttributeMaxDynamicSharedMemorySize, SMEM2_BYTES);
    cudaFuncSetAttribute(out_gemm_kernel,
                         cudaFuncAttributeMaxDynamicSharedMemorySize, SMEM_BYTES);

    float*    g_Z_ptr;    cudaGetSymbolAddress((void**)&g_Z_ptr, g_Z);
    float*    g_Sp1_ptr;  cudaGetSymbolAddress((void**)&g_Sp1_ptr, g_Sp1);
    uint32_t* g_x16_ptr;  cudaGetSymbolAddress((void**)&g_x16_ptr, g_x16);
    uint32_t* g_z16_ptr;  cudaGetSymbolAddress((void**)&g_z16_ptr, g_z16);

    // prep: adj -> bf16 + colsum partials (one streaming pass)
    prep_kernel<<<dim3(4, 32, B_SZ), 256>>>(adj);
    deg_reduce_kernel<<<(B_SZ * N_SZ) / 256, 256>>>();
    xpack_kernel<<<1024, 256>>>(x);

    // cheb1 (bf16): S1 = adj @ x ; h=0 -> slice1 raw, h=1 -> Sp1
    cheb16_kernel<<<dim3(32, B_SZ, 2), 256, SMEM2_BYTES>>>(
        g_x16_ptr, g_Z_ptr + NC, ZBATCH, g_Sp1_ptr, NC);
    combine1_kernel<<<1024, 256>>>(x);

    // cheb2 (bf16): S2 = adj @ Z1 ; h=0 -> slice2 raw, h=1 -> Sp1
    cheb16_kernel<<<dim3(32, B_SZ, 2), 256, SMEM2_BYTES>>>(
        g_z16_ptr, g_Z_ptr + 2 * NC, ZBATCH, g_Sp1_ptr, NC);
    combine2_kernel<<<(unsigned)((B_SZ * NC / 4) / 256), 256>>>(x);

    out_gemm_kernel<<<(B_SZ * N_SZ) / 128, 256, SMEM_BYTES>>>(W, out);
}